// round 3
// baseline (speedup 1.0000x reference)
#include <cuda_runtime.h>
#include <cuda_bf16.h>
#include <cstdint>

// ---------------------------------------------------------------------------
// Problem constants (fixed by setup_inputs)
// ---------------------------------------------------------------------------
#define BB   64          // batch
#define TT_  64          // encoder T == decoder TT
#define GG   11          // groups
#define FF   4           // features
#define HH   256         // hidden
#define EE   128         // embed
#define NT   3           // num_target
#define GT   (GG*BB)     // 704 rows per timestep  (r = t*GT + g*64 + b)
#define MTOT (TT_*GT)    // 45056
#define NG   1024        // 4*H gate width
#define KSZ  (256*1024)  // transposed weight slab

// ---------------------------------------------------------------------------
// Scratch (device globals: allocation-free rule)
// ---------------------------------------------------------------------------
__device__ float g_emb[MTOT*EE];
__device__ float g_X[MTOT*NG];           // input-projection + bias per layer
__device__ float g_Y0[MTOT*HH];
__device__ float g_Y1[MTOT*HH];
__device__ float g_Cst[GT*HH];
__device__ float g_encWih0T[EE*NG];
__device__ float g_encWihsT[3*KSZ];
__device__ float g_encWhhT[4*KSZ];
__device__ float g_biasEnc[4*NG];
__device__ float g_decWihsT[3*KSZ];
__device__ float g_decWhhT[3*KSZ];       // decoder layers 1..3
__device__ float g_WcPack[512*NG];       // [dec_Whh0 ; dec_Wih0[:, :256]] transposed
__device__ float g_decWeT[EE*NG];        // dec_Wih0[:, 256:384] transposed
__device__ float g_biasDec[4*NG];
__device__ float g_dech[4*BB*HH];
__device__ float g_decc[4*BB*HH];
__device__ float g_attn[BB*HH];
__device__ float g_cin[BB*512];
__device__ float g_const[4*BB*NG];
__device__ float g_e[NT*BB*EE];
__device__ float g_h1[NT*BB*HH];
__device__ float g_h2[NT*BB*HH];

__device__ __forceinline__ float sigmoidf(float x){ return 1.f/(1.f + expf(-x)); }

// ---------------------------------------------------------------------------
// Tiled transpose: dst[c*ldD + r] = src[r*ldS + c]
// ---------------------------------------------------------------------------
__global__ void transpose_k(const float* __restrict__ src, int ldS, int rows, int cols,
                            float* __restrict__ dst, int ldD)
{
    __shared__ float tile[32][33];
    int c0 = blockIdx.x*32, r0 = blockIdx.y*32;
    for (int i = threadIdx.y; i < 32; i += 8){
        int r = r0 + i, c = c0 + threadIdx.x;
        tile[i][threadIdx.x] = (r < rows && c < cols) ? src[(size_t)r*ldS + c] : 0.f;
    }
    __syncthreads();
    for (int i = threadIdx.y; i < 32; i += 8){
        int c = c0 + i, r = r0 + threadIdx.x;
        if (c < cols && r < rows) dst[(size_t)c*ldD + r] = tile[threadIdx.x][i];
    }
}

__global__ void addv_k(const float* a, const float* b, float* o, int n)
{
    int i = blockIdx.x*256 + threadIdx.x;
    if (i < n) o[i] = a[i] + b[i];
}

// ---------------------------------------------------------------------------
// emb[m][e] = relu(sum_f x[b,t,g,f]*Wlin[e,f] + b[e]),  m = t*704 + g*64 + b
// ---------------------------------------------------------------------------
__global__ void emb_k(const float* __restrict__ x, const float* __restrict__ W,
                      const float* __restrict__ bias, float* __restrict__ emb)
{
    int m = blockIdx.x;
    int t = m / GT; int rem = m % GT; int g = rem >> 6; int b = rem & 63;
    const float* xr = x + (((size_t)(b*TT_ + t))*GG + g)*FF;
    float x0 = xr[0], x1 = xr[1], x2 = xr[2], x3 = xr[3];
    int e = threadIdx.x;
    float v = bias[e] + x0*W[e*4] + x1*W[e*4+1] + x2*W[e*4+2] + x3*W[e*4+3];
    emb[(size_t)m*EE + e] = fmaxf(v, 0.f);
}

// ---------------------------------------------------------------------------
// SGEMM: C = A(MxK) @ B(KxN) + bias[n], 128x128 tile, BK=8, 256 threads
// ---------------------------------------------------------------------------
__global__ void gemm_k(const float* __restrict__ A, const float* __restrict__ B,
                       const float* __restrict__ bias, float* __restrict__ C,
                       int M, int N, int K)
{
    __shared__ float As[8][128];
    __shared__ float Bs[8][128];
    int tid = threadIdx.x;
    int m0 = blockIdx.y*128, n0 = blockIdx.x*128;
    int tx = tid & 15, ty = tid >> 4;
    float acc[8][8];
    #pragma unroll
    for (int i = 0; i < 8; i++)
        #pragma unroll
        for (int j = 0; j < 8; j++) acc[i][j] = 0.f;

    int arow = tid >> 1, acol = (tid & 1)*4;
    int brow = tid >> 5, bcol = (tid & 31)*4;

    for (int k0 = 0; k0 < K; k0 += 8){
        float4 av = make_float4(0.f,0.f,0.f,0.f);
        int gm = m0 + arow;
        if (gm < M) av = *reinterpret_cast<const float4*>(A + (size_t)gm*K + k0 + acol);
        As[acol+0][arow] = av.x; As[acol+1][arow] = av.y;
        As[acol+2][arow] = av.z; As[acol+3][arow] = av.w;
        *reinterpret_cast<float4*>(&Bs[brow][bcol]) =
            *reinterpret_cast<const float4*>(B + (size_t)(k0+brow)*N + n0 + bcol);
        __syncthreads();
        #pragma unroll
        for (int kk = 0; kk < 8; kk++){
            float a[8], b[8];
            *reinterpret_cast<float4*>(a)   = *reinterpret_cast<float4*>(&As[kk][ty*4]);
            *reinterpret_cast<float4*>(a+4) = *reinterpret_cast<float4*>(&As[kk][64+ty*4]);
            *reinterpret_cast<float4*>(b)   = *reinterpret_cast<float4*>(&Bs[kk][tx*4]);
            *reinterpret_cast<float4*>(b+4) = *reinterpret_cast<float4*>(&Bs[kk][64+tx*4]);
            #pragma unroll
            for (int i = 0; i < 8; i++)
                #pragma unroll
                for (int j = 0; j < 8; j++) acc[i][j] += a[i]*b[j];
        }
        __syncthreads();
    }
    #pragma unroll
    for (int i = 0; i < 8; i++){
        int gm = m0 + ((i < 4) ? (ty*4 + i) : (64 + ty*4 + (i-4)));
        if (gm >= M) continue;
        #pragma unroll
        for (int j = 0; j < 8; j++){
            int gn = n0 + ((j < 4) ? (tx*4 + j) : (64 + tx*4 + (j-4)));
            C[(size_t)gm*N + gn] = acc[i][j] + bias[gn];
        }
    }
}

// ---------------------------------------------------------------------------
// Fused LSTM step: gates = In(MxK) @ Wt(Kx1024) + cnst ; update c,h.
// cnst indexed per-row (cnstPerB=0) or per-batch b=m%64 (cnstPerB=1).
// Cin same indexing via cinPerB. Cout optional. first => In and Cin treated 0.
// Grid: (256/32 j-tiles, M/32 m-tiles), 256 threads.
// ---------------------------------------------------------------------------
__global__ void lstm_step_k(const float* __restrict__ In, int K,
                            const float* __restrict__ Wt,
                            const float* __restrict__ cnst, int cnstPerB,
                            const float* __restrict__ Cin, int cinPerB,
                            float* Cout, float* __restrict__ Hout, int first)
{
    __shared__ float sIn[32][33];
    __shared__ float sW[32][4][32];
    int tid = threadIdx.x;
    int tx = tid & 31, ty = tid >> 5;
    int m0 = blockIdx.y*32, j0 = blockIdx.x*32;
    float acc[4][4];
    #pragma unroll
    for (int i = 0; i < 4; i++)
        #pragma unroll
        for (int g = 0; g < 4; g++) acc[i][g] = 0.f;

    if (!first){
        int r = tid >> 3, kc = (tid & 7)*4;
        for (int k0 = 0; k0 < K; k0 += 32){
            float4 v = *reinterpret_cast<const float4*>(In + (size_t)(m0+r)*K + k0 + kc);
            sIn[r][kc] = v.x; sIn[r][kc+1] = v.y; sIn[r][kc+2] = v.z; sIn[r][kc+3] = v.w;
            #pragma unroll
            for (int q = 0; q < 16; q++){
                int lin = q*256 + tid;
                int kr = lin >> 7;
                int col = lin & 127;
                int gate = col >> 5, jc = col & 31;
                sW[kr][gate][jc] = Wt[(size_t)(k0+kr)*NG + gate*HH + j0 + jc];
            }
            __syncthreads();
            #pragma unroll
            for (int kk = 0; kk < 32; kk++){
                float w0 = sW[kk][0][tx], w1 = sW[kk][1][tx];
                float w2 = sW[kk][2][tx], w3 = sW[kk][3][tx];
                #pragma unroll
                for (int mi = 0; mi < 4; mi++){
                    float a = sIn[ty + mi*8][kk];
                    acc[mi][0] += a*w0; acc[mi][1] += a*w1;
                    acc[mi][2] += a*w2; acc[mi][3] += a*w3;
                }
            }
            __syncthreads();
        }
    }
    int j = j0 + tx;
    #pragma unroll
    for (int mi = 0; mi < 4; mi++){
        int m = m0 + ty + mi*8;
        int cr = cnstPerB ? (m & 63) : m;
        const float* cp = cnst + (size_t)cr*NG;
        float gi = acc[mi][0] + cp[j];
        float gf = acc[mi][1] + cp[HH + j];
        float gg = acc[mi][2] + cp[2*HH + j];
        float go = acc[mi][3] + cp[3*HH + j];
        float ig = sigmoidf(gi), fg = sigmoidf(gf);
        float gt = tanhf(gg),    og = sigmoidf(go);
        float cprev = first ? 0.f : Cin[(size_t)(cinPerB ? (m & 63) : m)*HH + j];
        float c2 = fg*cprev + ig*gt;
        if (Cout) Cout[(size_t)m*HH + j] = c2;
        Hout[(size_t)m*HH + j] = og * tanhf(c2);
    }
}

// ---------------------------------------------------------------------------
// Snapshot final (h, c) for group = *tord of one layer
// ---------------------------------------------------------------------------
__global__ void snap_k(const float* __restrict__ Yt, const float* __restrict__ C,
                       const int* __restrict__ tord, float* dh, float* dc)
{
    int b = blockIdx.x, h = threadIdx.x;
    int row = (*tord)*64 + b;
    dh[b*HH + h] = Yt[(size_t)row*HH + h];
    dc[b*HH + h] = C[(size_t)row*HH + h];
}

// ---------------------------------------------------------------------------
// Attention: per-batch softmax over 704 (g,t) scores; the hq.wa_h + attn_b
// term is constant per b and cancels in softmax -> skipped.
// ---------------------------------------------------------------------------
__global__ void attn_k(const float* __restrict__ Y3, const float* __restrict__ attnW,
                       float* __restrict__ attn)
{
    int b = blockIdx.x, tid = threadIdx.x;
    __shared__ float wae[HH];
    __shared__ float sc[GT];
    __shared__ float red[256];
    wae[tid] = attnW[HH + tid];
    __syncthreads();
    for (int idx = tid; idx < GT; idx += 256){
        int g = idx % GG, t = idx / GG;
        const float* row = Y3 + ((size_t)(t*GT + g*64 + b))*HH;
        float s = 0.f;
        #pragma unroll 4
        for (int h = 0; h < HH; h++) s += row[h]*wae[h];
        sc[idx] = s;
    }
    __syncthreads();
    float mx = -1e30f;
    for (int idx = tid; idx < GT; idx += 256) mx = fmaxf(mx, sc[idx]);
    red[tid] = mx; __syncthreads();
    for (int s = 128; s > 0; s >>= 1){ if (tid < s) red[tid] = fmaxf(red[tid], red[tid+s]); __syncthreads(); }
    mx = red[0]; __syncthreads();
    float sm = 0.f;
    for (int idx = tid; idx < GT; idx += 256){ float e = expf(sc[idx]-mx); sc[idx] = e; sm += e; }
    red[tid] = sm; __syncthreads();
    for (int s = 128; s > 0; s >>= 1){ if (tid < s) red[tid] += red[tid+s]; __syncthreads(); }
    float inv = 1.f/red[0];
    __syncthreads();
    float a0 = 0.f;
    for (int idx = 0; idx < GT; idx++){
        int g = idx % GG, t = idx / GG;
        a0 += sc[idx]*Y3[((size_t)(t*GT + g*64 + b))*HH + tid];
    }
    attn[b*HH + tid] = a0*inv;
}

__global__ void pack_cin_k(const float* dh0, const float* attn, float* cin)
{
    int b = blockIdx.x, k = threadIdx.x;
    cin[b*512 + k] = (k < HH) ? dh0[b*HH + k] : attn[b*HH + (k - HH)];
}

// ---------------------------------------------------------------------------
// Decoder init: e0[r] = relu(x[b,63,tord+j,:] @ Wemb^T + bemb),  r = j*64+b
// ---------------------------------------------------------------------------
__global__ void dec_init_k(const float* __restrict__ x, const float* __restrict__ Wemb,
                           const float* __restrict__ bemb, const int* __restrict__ tord,
                           float* __restrict__ e)
{
    int r = blockIdx.x; int j = r >> 6, b = r & 63;
    int tid = threadIdx.x;
    int g = *tord + j;
    const float* xr = x + (((size_t)(b*TT_ + 63))*GG + g)*FF;
    float v = bemb[tid];
    #pragma unroll
    for (int f = 0; f < 4; f++) v += xr[f]*Wemb[tid*4 + f];
    e[r*EE + tid] = fmaxf(v, 0.f);
}

// ---------------------------------------------------------------------------
// Decoder epilogue: out = top @ outW^T + outb (written to d_out[b][t][j]);
// e_next = relu(out @ Wemb^T + bemb)
// ---------------------------------------------------------------------------
__global__ void dec_out_k(const float* __restrict__ top, const float* __restrict__ outW,
                          const float* __restrict__ outb, const float* __restrict__ Wemb,
                          const float* __restrict__ bemb, float* __restrict__ dout,
                          int t, float* __restrict__ enext)
{
    int r = blockIdx.x; int j = r >> 6, b = r & 63;
    int tid = threadIdx.x;
    __shared__ float st[HH];
    __shared__ float so[4];
    st[tid] = top[(size_t)r*HH + tid];
    st[tid + 128] = top[(size_t)r*HH + 128 + tid];
    __syncthreads();
    int w = tid >> 5, lane = tid & 31;
    float s = 0.f;
    for (int h = lane; h < HH; h += 32) s += st[h]*outW[w*HH + h];
    #pragma unroll
    for (int o = 16; o; o >>= 1) s += __shfl_down_sync(0xffffffff, s, o);
    if (lane == 0){
        s += outb[w];
        so[w] = s;
        dout[(size_t)b*(TT_*NT*FF) + t*(NT*FF) + j*FF + w] = s;
    }
    __syncthreads();
    float e = bemb[tid];
    #pragma unroll
    for (int f = 0; f < 4; f++) e += so[f]*Wemb[tid*4 + f];
    enext[r*EE + tid] = fmaxf(e, 0.f);
}

// ---------------------------------------------------------------------------
// host
// ---------------------------------------------------------------------------
static float* symaddr(const void* sym)
{
    void* p = nullptr;
    cudaGetSymbolAddress(&p, sym);
    return (float*)p;
}

extern "C" void kernel_launch(void* const* d_in, const int* in_sizes, int n_in,
                              void* d_out, int out_size)
{
    (void)in_sizes; (void)n_in; (void)out_size;
    const float* x        = (const float*)d_in[0];
    const float* encLinW  = (const float*)d_in[2];
    const float* encLinB  = (const float*)d_in[3];
    const float* encWih0  = (const float*)d_in[4];
    const float* encWihs  = (const float*)d_in[5];
    const float* encWhh   = (const float*)d_in[6];
    const float* encBih   = (const float*)d_in[7];
    const float* encBhh   = (const float*)d_in[8];
    const float* decEmbW  = (const float*)d_in[9];
    const float* decEmbB  = (const float*)d_in[10];
    const float* attnW    = (const float*)d_in[11];
    const float* decWih0  = (const float*)d_in[13];
    const float* decWihs  = (const float*)d_in[14];
    const float* decWhh   = (const float*)d_in[15];
    const float* decBih   = (const float*)d_in[16];
    const float* decBhh   = (const float*)d_in[17];
    const float* outW     = (const float*)d_in[18];
    const float* outB     = (const float*)d_in[19];
    const int*   tord     = (const int*)d_in[20];
    float* out = (float*)d_out;

    float* pEmb      = symaddr(g_emb);
    float* pX        = symaddr(g_X);
    float* pY0       = symaddr(g_Y0);
    float* pY1       = symaddr(g_Y1);
    float* pC        = symaddr(g_Cst);
    float* pWih0T    = symaddr(g_encWih0T);
    float* pWihsT    = symaddr(g_encWihsT);
    float* pWhhT     = symaddr(g_encWhhT);
    float* pBiasEnc  = symaddr(g_biasEnc);
    float* pDecWihsT = symaddr(g_decWihsT);
    float* pDecWhhT  = symaddr(g_decWhhT);
    float* pPack     = symaddr(g_WcPack);
    float* pWeT      = symaddr(g_decWeT);
    float* pBiasDec  = symaddr(g_biasDec);
    float* pDech     = symaddr(g_dech);
    float* pDecc     = symaddr(g_decc);
    float* pAttn     = symaddr(g_attn);
    float* pCin      = symaddr(g_cin);
    float* pConst    = symaddr(g_const);
    float* pE        = symaddr(g_e);
    float* pH1       = symaddr(g_h1);
    float* pH2       = symaddr(g_h2);

    dim3 tb(32, 8);
    // ---- weight prep (transposes + bias folds) ----
    transpose_k<<<dim3(4, 32), tb>>>(encWih0, EE, NG, EE, pWih0T, NG);
    for (int l = 0; l < 3; l++)
        transpose_k<<<dim3(8, 32), tb>>>(encWihs + (size_t)l*NG*HH, HH, NG, HH,
                                         pWihsT + (size_t)l*KSZ, NG);
    for (int l = 0; l < 4; l++)
        transpose_k<<<dim3(8, 32), tb>>>(encWhh + (size_t)l*NG*HH, HH, NG, HH,
                                         pWhhT + (size_t)l*KSZ, NG);
    addv_k<<<16, 256>>>(encBih, encBhh, pBiasEnc, 4*NG);
    for (int l = 0; l < 3; l++)
        transpose_k<<<dim3(8, 32), tb>>>(decWihs + (size_t)l*NG*HH, HH, NG, HH,
                                         pDecWihsT + (size_t)l*KSZ, NG);
    for (int l = 1; l < 4; l++)
        transpose_k<<<dim3(8, 32), tb>>>(decWhh + (size_t)l*NG*HH, HH, NG, HH,
                                         pDecWhhT + (size_t)(l-1)*KSZ, NG);
    transpose_k<<<dim3(8, 32), tb>>>(decWhh, HH, NG, HH, pPack, NG);
    transpose_k<<<dim3(8, 32), tb>>>(decWih0, 384, NG, HH, pPack + (size_t)HH*NG, NG);
    transpose_k<<<dim3(4, 32), tb>>>(decWih0 + HH, 384, NG, EE, pWeT, NG);
    addv_k<<<16, 256>>>(decBih, decBhh, pBiasDec, 4*NG);

    // ---- encoder embedding ----
    emb_k<<<MTOT, 128>>>(x, encLinW, encLinB, pEmb);

    // ---- encoder: 4 layers, layer-sequential ----
    const float* Ain = pEmb;
    int Kin = EE;
    const float* WT = pWih0T;
    float* Ybuf[2] = { pY0, pY1 };
    for (int l = 0; l < 4; l++){
        gemm_k<<<dim3(8, MTOT/128), 256>>>(Ain, WT, pBiasEnc + l*NG, pX, MTOT, NG, Kin);
        float* Yc = Ybuf[l & 1];
        for (int t = 0; t < TT_; t++){
            const float* Hprev = (t == 0) ? nullptr : (Yc + (size_t)(t-1)*GT*HH);
            lstm_step_k<<<dim3(8, GT/32), 256>>>(Hprev, HH, pWhhT + (size_t)l*KSZ,
                                                 pX + (size_t)t*GT*NG, 0,
                                                 pC, 0, pC,
                                                 Yc + (size_t)t*GT*HH, t == 0);
        }
        snap_k<<<64, 256>>>(Yc + (size_t)(TT_-1)*GT*HH, pC, tord,
                            pDech + (size_t)l*BB*HH, pDecc + (size_t)l*BB*HH);
        Ain = Yc; Kin = HH; WT = pWihsT + (size_t)l*KSZ;   // next layer uses Wihs[l]
    }
    float* Ytop = pY1;  // layer 3 output

    // ---- attention ----
    attn_k<<<BB, 256>>>(Ytop, attnW, pAttn);

    // ---- decoder constants: const_l = h[l]@Whh_l^T (+ attn@Wih0[:, :256]^T for l=0) + biases ----
    pack_cin_k<<<BB, 512>>>(pDech, pAttn, pCin);
    gemm_k<<<dim3(8, 1), 256>>>(pCin, pPack, pBiasDec, pConst, BB, NG, 512);
    for (int l = 1; l < 4; l++)
        gemm_k<<<dim3(8, 1), 256>>>(pDech + (size_t)l*BB*HH, pDecWhhT + (size_t)(l-1)*KSZ,
                                    pBiasDec + l*NG, pConst + (size_t)l*BB*NG, BB, NG, HH);

    // ---- decoder: 64 steps, 3 targets batched (M = 192) ----
    dec_init_k<<<NT*BB, 128>>>(x, decEmbW, decEmbB, tord, pE);
    for (int t = 0; t < TT_; t++){
        lstm_step_k<<<dim3(8, 6), 256>>>(pE, EE, pWeT, pConst, 1,
                                         pDecc, 1, nullptr, pH1, 0);
        lstm_step_k<<<dim3(8, 6), 256>>>(pH1, HH, pDecWihsT, pConst + (size_t)BB*NG, 1,
                                         pDecc + (size_t)BB*HH, 1, nullptr, pH2, 0);
        lstm_step_k<<<dim3(8, 6), 256>>>(pH2, HH, pDecWihsT + KSZ, pConst + (size_t)2*BB*NG, 1,
                                         pDecc + (size_t)2*BB*HH, 1, nullptr, pH1, 0);
        lstm_step_k<<<dim3(8, 6), 256>>>(pH1, HH, pDecWihsT + 2*KSZ, pConst + (size_t)3*BB*NG, 1,
                                         pDecc + (size_t)3*BB*HH, 1, nullptr, pH2, 0);
        dec_out_k<<<NT*BB, 128>>>(pH2, outW, outB, decEmbW, decEmbB, out, t, pE);
    }
}

// round 4
// speedup vs baseline: 1.0005x; 1.0005x over previous
#include <cuda_runtime.h>
#include <cuda_bf16.h>
#include <cstdint>

// ---------------------------------------------------------------------------
// Problem constants (fixed by setup_inputs)
// ---------------------------------------------------------------------------
#define BB   64          // batch
#define TT_  64          // encoder T == decoder TT
#define GG   11          // groups
#define FF   4           // features
#define HH   256         // hidden
#define EE   128         // embed
#define NT   3           // num_target
#define GT   (GG*BB)     // 704 rows per timestep  (r = t*GT + g*64 + b)
#define MTOT (TT_*GT)    // 45056
#define NG   1024        // 4*H gate width
#define KSZ  (256*1024)  // transposed weight slab

// ---------------------------------------------------------------------------
// Scratch (device globals: allocation-free rule)
// ---------------------------------------------------------------------------
__device__ float g_emb[MTOT*EE];
__device__ float g_X[MTOT*NG];           // input-projection + bias per layer
__device__ float g_Y0[MTOT*HH];
__device__ float g_Y1[MTOT*HH];
__device__ float g_Cst[GT*HH];
__device__ float g_encWih0T[EE*NG];
__device__ float g_encWihsT[3*KSZ];
__device__ float g_encWhhT[4*KSZ];
__device__ float g_biasEnc[4*NG];
__device__ float g_decWihsT[3*KSZ];
__device__ float g_decWhhT[3*KSZ];       // decoder layers 1..3
__device__ float g_WcPack[512*NG];       // [dec_Whh0 ; dec_Wih0[:, :256]] transposed
__device__ float g_decWeT[EE*NG];        // dec_Wih0[:, 256:384] transposed
__device__ float g_biasDec[4*NG];
__device__ float g_dech[4*BB*HH];
__device__ float g_decc[4*BB*HH];
__device__ float g_attn[BB*HH];
__device__ float g_cin[BB*512];
__device__ float g_const[4*BB*NG];
__device__ float g_e[NT*BB*EE];
__device__ float g_h1[NT*BB*HH];
__device__ float g_h2[NT*BB*HH];

__device__ __forceinline__ float sigmoidf(float x){ return 1.f/(1.f + expf(-x)); }

// ---------------------------------------------------------------------------
// Tiled transpose: dst[c*ldD + r] = src[r*ldS + c]
// ---------------------------------------------------------------------------
__global__ void transpose_k(const float* __restrict__ src, int ldS, int rows, int cols,
                            float* __restrict__ dst, int ldD)
{
    __shared__ float tile[32][33];
    int c0 = blockIdx.x*32, r0 = blockIdx.y*32;
    for (int i = threadIdx.y; i < 32; i += 8){
        int r = r0 + i, c = c0 + threadIdx.x;
        tile[i][threadIdx.x] = (r < rows && c < cols) ? src[(size_t)r*ldS + c] : 0.f;
    }
    __syncthreads();
    for (int i = threadIdx.y; i < 32; i += 8){
        int c = c0 + i, r = r0 + threadIdx.x;
        if (c < cols && r < rows) dst[(size_t)c*ldD + r] = tile[threadIdx.x][i];
    }
}

__global__ void addv_k(const float* a, const float* b, float* o, int n)
{
    int i = blockIdx.x*256 + threadIdx.x;
    if (i < n) o[i] = a[i] + b[i];
}

// ---------------------------------------------------------------------------
// emb[m][e] = relu(sum_f x[b,t,g,f]*Wlin[e,f] + b[e]),  m = t*704 + g*64 + b
// ---------------------------------------------------------------------------
__global__ void emb_k(const float* __restrict__ x, const float* __restrict__ W,
                      const float* __restrict__ bias, float* __restrict__ emb)
{
    int m = blockIdx.x;
    int t = m / GT; int rem = m % GT; int g = rem >> 6; int b = rem & 63;
    const float* xr = x + (((size_t)(b*TT_ + t))*GG + g)*FF;
    float x0 = xr[0], x1 = xr[1], x2 = xr[2], x3 = xr[3];
    int e = threadIdx.x;
    float v = bias[e] + x0*W[e*4] + x1*W[e*4+1] + x2*W[e*4+2] + x3*W[e*4+3];
    emb[(size_t)m*EE + e] = fmaxf(v, 0.f);
}

// ---------------------------------------------------------------------------
// SGEMM: C = A(MxK) @ B(KxN) + bias[n], 128x128 tile, BK=8, 256 threads
// ---------------------------------------------------------------------------
__global__ void gemm_k(const float* __restrict__ A, const float* __restrict__ B,
                       const float* __restrict__ bias, float* __restrict__ C,
                       int M, int N, int K)
{
    __shared__ float As[8][128];
    __shared__ float Bs[8][128];
    int tid = threadIdx.x;
    int m0 = blockIdx.y*128, n0 = blockIdx.x*128;
    int tx = tid & 15, ty = tid >> 4;
    float acc[8][8];
    #pragma unroll
    for (int i = 0; i < 8; i++)
        #pragma unroll
        for (int j = 0; j < 8; j++) acc[i][j] = 0.f;

    int arow = tid >> 1, acol = (tid & 1)*4;
    int brow = tid >> 5, bcol = (tid & 31)*4;

    for (int k0 = 0; k0 < K; k0 += 8){
        float4 av = make_float4(0.f,0.f,0.f,0.f);
        int gm = m0 + arow;
        if (gm < M) av = *reinterpret_cast<const float4*>(A + (size_t)gm*K + k0 + acol);
        As[acol+0][arow] = av.x; As[acol+1][arow] = av.y;
        As[acol+2][arow] = av.z; As[acol+3][arow] = av.w;
        *reinterpret_cast<float4*>(&Bs[brow][bcol]) =
            *reinterpret_cast<const float4*>(B + (size_t)(k0+brow)*N + n0 + bcol);
        __syncthreads();
        #pragma unroll
        for (int kk = 0; kk < 8; kk++){
            float a[8], b[8];
            *reinterpret_cast<float4*>(a)   = *reinterpret_cast<float4*>(&As[kk][ty*4]);
            *reinterpret_cast<float4*>(a+4) = *reinterpret_cast<float4*>(&As[kk][64+ty*4]);
            *reinterpret_cast<float4*>(b)   = *reinterpret_cast<float4*>(&Bs[kk][tx*4]);
            *reinterpret_cast<float4*>(b+4) = *reinterpret_cast<float4*>(&Bs[kk][64+tx*4]);
            #pragma unroll
            for (int i = 0; i < 8; i++)
                #pragma unroll
                for (int j = 0; j < 8; j++) acc[i][j] += a[i]*b[j];
        }
        __syncthreads();
    }
    #pragma unroll
    for (int i = 0; i < 8; i++){
        int gm = m0 + ((i < 4) ? (ty*4 + i) : (64 + ty*4 + (i-4)));
        if (gm >= M) continue;
        #pragma unroll
        for (int j = 0; j < 8; j++){
            int gn = n0 + ((j < 4) ? (tx*4 + j) : (64 + tx*4 + (j-4)));
            C[(size_t)gm*N + gn] = acc[i][j] + bias[gn];
        }
    }
}

// ---------------------------------------------------------------------------
// Fused LSTM step: gates = In(MxK) @ Wt(Kx1024) + cnst ; update c,h.
// cnst indexed per-row (cnstPerB=0) or per-batch b=m%64 (cnstPerB=1).
// Cin same indexing via cinPerB. Cout optional. first => In and Cin treated 0.
// Grid: (256/32 j-tiles, M/32 m-tiles), 256 threads.
// ---------------------------------------------------------------------------
__global__ void lstm_step_k(const float* __restrict__ In, int K,
                            const float* __restrict__ Wt,
                            const float* __restrict__ cnst, int cnstPerB,
                            const float* __restrict__ Cin, int cinPerB,
                            float* Cout, float* __restrict__ Hout, int first)
{
    __shared__ float sIn[32][33];
    __shared__ float sW[32][4][32];
    int tid = threadIdx.x;
    int tx = tid & 31, ty = tid >> 5;
    int m0 = blockIdx.y*32, j0 = blockIdx.x*32;
    float acc[4][4];
    #pragma unroll
    for (int i = 0; i < 4; i++)
        #pragma unroll
        for (int g = 0; g < 4; g++) acc[i][g] = 0.f;

    if (!first){
        int r = tid >> 3, kc = (tid & 7)*4;
        for (int k0 = 0; k0 < K; k0 += 32){
            float4 v = *reinterpret_cast<const float4*>(In + (size_t)(m0+r)*K + k0 + kc);
            sIn[r][kc] = v.x; sIn[r][kc+1] = v.y; sIn[r][kc+2] = v.z; sIn[r][kc+3] = v.w;
            #pragma unroll
            for (int q = 0; q < 16; q++){
                int lin = q*256 + tid;
                int kr = lin >> 7;
                int col = lin & 127;
                int gate = col >> 5, jc = col & 31;
                sW[kr][gate][jc] = Wt[(size_t)(k0+kr)*NG + gate*HH + j0 + jc];
            }
            __syncthreads();
            #pragma unroll
            for (int kk = 0; kk < 32; kk++){
                float w0 = sW[kk][0][tx], w1 = sW[kk][1][tx];
                float w2 = sW[kk][2][tx], w3 = sW[kk][3][tx];
                #pragma unroll
                for (int mi = 0; mi < 4; mi++){
                    float a = sIn[ty + mi*8][kk];
                    acc[mi][0] += a*w0; acc[mi][1] += a*w1;
                    acc[mi][2] += a*w2; acc[mi][3] += a*w3;
                }
            }
            __syncthreads();
        }
    }
    int j = j0 + tx;
    #pragma unroll
    for (int mi = 0; mi < 4; mi++){
        int m = m0 + ty + mi*8;
        int cr = cnstPerB ? (m & 63) : m;
        const float* cp = cnst + (size_t)cr*NG;
        float gi = acc[mi][0] + cp[j];
        float gf = acc[mi][1] + cp[HH + j];
        float gg = acc[mi][2] + cp[2*HH + j];
        float go = acc[mi][3] + cp[3*HH + j];
        float ig = sigmoidf(gi), fg = sigmoidf(gf);
        float gt = tanhf(gg),    og = sigmoidf(go);
        float cprev = first ? 0.f : Cin[(size_t)(cinPerB ? (m & 63) : m)*HH + j];
        float c2 = fg*cprev + ig*gt;
        if (Cout) Cout[(size_t)m*HH + j] = c2;
        Hout[(size_t)m*HH + j] = og * tanhf(c2);
    }
}

// ---------------------------------------------------------------------------
// Snapshot final (h, c) for group = *tord of one layer
// ---------------------------------------------------------------------------
__global__ void snap_k(const float* __restrict__ Yt, const float* __restrict__ C,
                       const int* __restrict__ tord, float* dh, float* dc)
{
    int b = blockIdx.x, h = threadIdx.x;
    int row = (*tord)*64 + b;
    dh[b*HH + h] = Yt[(size_t)row*HH + h];
    dc[b*HH + h] = C[(size_t)row*HH + h];
}

// ---------------------------------------------------------------------------
// Attention: per-batch softmax over 704 (g,t) scores; the hq.wa_h + attn_b
// term is constant per b and cancels in softmax -> skipped.
// ---------------------------------------------------------------------------
__global__ void attn_k(const float* __restrict__ Y3, const float* __restrict__ attnW,
                       float* __restrict__ attn)
{
    int b = blockIdx.x, tid = threadIdx.x;
    __shared__ float wae[HH];
    __shared__ float sc[GT];
    __shared__ float red[256];
    wae[tid] = attnW[HH + tid];
    __syncthreads();
    for (int idx = tid; idx < GT; idx += 256){
        int g = idx % GG, t = idx / GG;
        const float* row = Y3 + ((size_t)(t*GT + g*64 + b))*HH;
        float s = 0.f;
        #pragma unroll 4
        for (int h = 0; h < HH; h++) s += row[h]*wae[h];
        sc[idx] = s;
    }
    __syncthreads();
    float mx = -1e30f;
    for (int idx = tid; idx < GT; idx += 256) mx = fmaxf(mx, sc[idx]);
    red[tid] = mx; __syncthreads();
    for (int s = 128; s > 0; s >>= 1){ if (tid < s) red[tid] = fmaxf(red[tid], red[tid+s]); __syncthreads(); }
    mx = red[0]; __syncthreads();
    float sm = 0.f;
    for (int idx = tid; idx < GT; idx += 256){ float e = expf(sc[idx]-mx); sc[idx] = e; sm += e; }
    red[tid] = sm; __syncthreads();
    for (int s = 128; s > 0; s >>= 1){ if (tid < s) red[tid] += red[tid+s]; __syncthreads(); }
    float inv = 1.f/red[0];
    __syncthreads();
    float a0 = 0.f;
    for (int idx = 0; idx < GT; idx++){
        int g = idx % GG, t = idx / GG;
        a0 += sc[idx]*Y3[((size_t)(t*GT + g*64 + b))*HH + tid];
    }
    attn[b*HH + tid] = a0*inv;
}

__global__ void pack_cin_k(const float* dh0, const float* attn, float* cin)
{
    int b = blockIdx.x, k = threadIdx.x;
    cin[b*512 + k] = (k < HH) ? dh0[b*HH + k] : attn[b*HH + (k - HH)];
}

// ---------------------------------------------------------------------------
// Decoder init: e0[r] = relu(x[b,63,tord+j,:] @ Wemb^T + bemb),  r = j*64+b
// ---------------------------------------------------------------------------
__global__ void dec_init_k(const float* __restrict__ x, const float* __restrict__ Wemb,
                           const float* __restrict__ bemb, const int* __restrict__ tord,
                           float* __restrict__ e)
{
    int r = blockIdx.x; int j = r >> 6, b = r & 63;
    int tid = threadIdx.x;
    int g = *tord + j;
    const float* xr = x + (((size_t)(b*TT_ + 63))*GG + g)*FF;
    float v = bemb[tid];
    #pragma unroll
    for (int f = 0; f < 4; f++) v += xr[f]*Wemb[tid*4 + f];
    e[r*EE + tid] = fmaxf(v, 0.f);
}

// ---------------------------------------------------------------------------
// Decoder epilogue: out = top @ outW^T + outb (written to d_out[b][t][j]);
// e_next = relu(out @ Wemb^T + bemb)
// ---------------------------------------------------------------------------
__global__ void dec_out_k(const float* __restrict__ top, const float* __restrict__ outW,
                          const float* __restrict__ outb, const float* __restrict__ Wemb,
                          const float* __restrict__ bemb, float* __restrict__ dout,
                          int t, float* __restrict__ enext)
{
    int r = blockIdx.x; int j = r >> 6, b = r & 63;
    int tid = threadIdx.x;
    __shared__ float st[HH];
    __shared__ float so[4];
    st[tid] = top[(size_t)r*HH + tid];
    st[tid + 128] = top[(size_t)r*HH + 128 + tid];
    __syncthreads();
    int w = tid >> 5, lane = tid & 31;
    float s = 0.f;
    for (int h = lane; h < HH; h += 32) s += st[h]*outW[w*HH + h];
    #pragma unroll
    for (int o = 16; o; o >>= 1) s += __shfl_down_sync(0xffffffff, s, o);
    if (lane == 0){
        s += outb[w];
        so[w] = s;
        dout[(size_t)b*(TT_*NT*FF) + t*(NT*FF) + j*FF + w] = s;
    }
    __syncthreads();
    float e = bemb[tid];
    #pragma unroll
    for (int f = 0; f < 4; f++) e += so[f]*Wemb[tid*4 + f];
    enext[r*EE + tid] = fmaxf(e, 0.f);
}

// ---------------------------------------------------------------------------
// host
// ---------------------------------------------------------------------------
static float* symaddr(const void* sym)
{
    void* p = nullptr;
    cudaGetSymbolAddress(&p, sym);
    return (float*)p;
}

extern "C" void kernel_launch(void* const* d_in, const int* in_sizes, int n_in,
                              void* d_out, int out_size)
{
    (void)in_sizes; (void)n_in; (void)out_size;
    const float* x        = (const float*)d_in[0];
    const float* encLinW  = (const float*)d_in[2];
    const float* encLinB  = (const float*)d_in[3];
    const float* encWih0  = (const float*)d_in[4];
    const float* encWihs  = (const float*)d_in[5];
    const float* encWhh   = (const float*)d_in[6];
    const float* encBih   = (const float*)d_in[7];
    const float* encBhh   = (const float*)d_in[8];
    const float* decEmbW  = (const float*)d_in[9];
    const float* decEmbB  = (const float*)d_in[10];
    const float* attnW    = (const float*)d_in[11];
    const float* decWih0  = (const float*)d_in[13];
    const float* decWihs  = (const float*)d_in[14];
    const float* decWhh   = (const float*)d_in[15];
    const float* decBih   = (const float*)d_in[16];
    const float* decBhh   = (const float*)d_in[17];
    const float* outW     = (const float*)d_in[18];
    const float* outB     = (const float*)d_in[19];
    const int*   tord     = (const int*)d_in[20];
    float* out = (float*)d_out;

    float* pEmb      = symaddr(g_emb);
    float* pX        = symaddr(g_X);
    float* pY0       = symaddr(g_Y0);
    float* pY1       = symaddr(g_Y1);
    float* pC        = symaddr(g_Cst);
    float* pWih0T    = symaddr(g_encWih0T);
    float* pWihsT    = symaddr(g_encWihsT);
    float* pWhhT     = symaddr(g_encWhhT);
    float* pBiasEnc  = symaddr(g_biasEnc);
    float* pDecWihsT = symaddr(g_decWihsT);
    float* pDecWhhT  = symaddr(g_decWhhT);
    float* pPack     = symaddr(g_WcPack);
    float* pWeT      = symaddr(g_decWeT);
    float* pBiasDec  = symaddr(g_biasDec);
    float* pDech     = symaddr(g_dech);
    float* pDecc     = symaddr(g_decc);
    float* pAttn     = symaddr(g_attn);
    float* pCin      = symaddr(g_cin);
    float* pConst    = symaddr(g_const);
    float* pE        = symaddr(g_e);
    float* pH1       = symaddr(g_h1);
    float* pH2       = symaddr(g_h2);

    dim3 tb(32, 8);
    // ---- weight prep (transposes + bias folds) ----
    transpose_k<<<dim3(4, 32), tb>>>(encWih0, EE, NG, EE, pWih0T, NG);
    for (int l = 0; l < 3; l++)
        transpose_k<<<dim3(8, 32), tb>>>(encWihs + (size_t)l*NG*HH, HH, NG, HH,
                                         pWihsT + (size_t)l*KSZ, NG);
    for (int l = 0; l < 4; l++)
        transpose_k<<<dim3(8, 32), tb>>>(encWhh + (size_t)l*NG*HH, HH, NG, HH,
                                         pWhhT + (size_t)l*KSZ, NG);
    addv_k<<<16, 256>>>(encBih, encBhh, pBiasEnc, 4*NG);
    for (int l = 0; l < 3; l++)
        transpose_k<<<dim3(8, 32), tb>>>(decWihs + (size_t)l*NG*HH, HH, NG, HH,
                                         pDecWihsT + (size_t)l*KSZ, NG);
    for (int l = 1; l < 4; l++)
        transpose_k<<<dim3(8, 32), tb>>>(decWhh + (size_t)l*NG*HH, HH, NG, HH,
                                         pDecWhhT + (size_t)(l-1)*KSZ, NG);
    transpose_k<<<dim3(8, 32), tb>>>(decWhh, HH, NG, HH, pPack, NG);
    transpose_k<<<dim3(8, 32), tb>>>(decWih0, 384, NG, HH, pPack + (size_t)HH*NG, NG);
    transpose_k<<<dim3(4, 32), tb>>>(decWih0 + HH, 384, NG, EE, pWeT, NG);
    addv_k<<<16, 256>>>(decBih, decBhh, pBiasDec, 4*NG);

    // ---- encoder embedding ----
    emb_k<<<MTOT, 128>>>(x, encLinW, encLinB, pEmb);

    // ---- encoder: 4 layers, layer-sequential ----
    const float* Ain = pEmb;
    int Kin = EE;
    const float* WT = pWih0T;
    float* Ybuf[2] = { pY0, pY1 };
    for (int l = 0; l < 4; l++){
        gemm_k<<<dim3(8, MTOT/128), 256>>>(Ain, WT, pBiasEnc + l*NG, pX, MTOT, NG, Kin);
        float* Yc = Ybuf[l & 1];
        for (int t = 0; t < TT_; t++){
            const float* Hprev = (t == 0) ? nullptr : (Yc + (size_t)(t-1)*GT*HH);
            lstm_step_k<<<dim3(8, GT/32), 256>>>(Hprev, HH, pWhhT + (size_t)l*KSZ,
                                                 pX + (size_t)t*GT*NG, 0,
                                                 pC, 0, pC,
                                                 Yc + (size_t)t*GT*HH, t == 0);
        }
        snap_k<<<64, 256>>>(Yc + (size_t)(TT_-1)*GT*HH, pC, tord,
                            pDech + (size_t)l*BB*HH, pDecc + (size_t)l*BB*HH);
        Ain = Yc; Kin = HH; WT = pWihsT + (size_t)l*KSZ;   // next layer uses Wihs[l]
    }
    float* Ytop = pY1;  // layer 3 output

    // ---- attention ----
    attn_k<<<BB, 256>>>(Ytop, attnW, pAttn);

    // ---- decoder constants: const_l = h[l]@Whh_l^T (+ attn@Wih0[:, :256]^T for l=0) + biases ----
    pack_cin_k<<<BB, 512>>>(pDech, pAttn, pCin);
    gemm_k<<<dim3(8, 1), 256>>>(pCin, pPack, pBiasDec, pConst, BB, NG, 512);
    for (int l = 1; l < 4; l++)
        gemm_k<<<dim3(8, 1), 256>>>(pDech + (size_t)l*BB*HH, pDecWhhT + (size_t)(l-1)*KSZ,
                                    pBiasDec + l*NG, pConst + (size_t)l*BB*NG, BB, NG, HH);

    // ---- decoder: 64 steps, 3 targets batched (M = 192) ----
    dec_init_k<<<NT*BB, 128>>>(x, decEmbW, decEmbB, tord, pE);
    for (int t = 0; t < TT_; t++){
        lstm_step_k<<<dim3(8, 6), 256>>>(pE, EE, pWeT, pConst, 1,
                                         pDecc, 1, nullptr, pH1, 0);
        lstm_step_k<<<dim3(8, 6), 256>>>(pH1, HH, pDecWihsT, pConst + (size_t)BB*NG, 1,
                                         pDecc + (size_t)BB*HH, 1, nullptr, pH2, 0);
        lstm_step_k<<<dim3(8, 6), 256>>>(pH2, HH, pDecWihsT + KSZ, pConst + (size_t)2*BB*NG, 1,
                                         pDecc + (size_t)2*BB*HH, 1, nullptr, pH1, 0);
        lstm_step_k<<<dim3(8, 6), 256>>>(pH1, HH, pDecWihsT + 2*KSZ, pConst + (size_t)3*BB*NG, 1,
                                         pDecc + (size_t)3*BB*HH, 1, nullptr, pH2, 0);
        dec_out_k<<<NT*BB, 128>>>(pH2, outW, outB, decEmbW, decEmbB, out, t, pE);
    }
}

// round 5
// speedup vs baseline: 1.1974x; 1.1967x over previous
#include <cuda_runtime.h>
#include <cstdint>

#define BB   64
#define TT_  64
#define GG   11
#define FF   4
#define HH   256
#define EE   128
#define NT   3
#define GT   (GG*BB)     // 704
#define MTOT (TT_*GT)    // 45056
#define NG   1024
#define KSZ  (256*1024)

__device__ float g_emb[MTOT*EE];
__device__ float g_X[MTOT*NG];
__device__ float g_Y0[MTOT*HH];
__device__ float g_Y1[MTOT*HH];
__device__ float g_Cst[GT*HH];
__device__ float g_encWih0T[EE*NG];
__device__ float g_encWihsT[3*KSZ];
__device__ float g_encWhhT[4*KSZ];
__device__ float g_biasEnc[4*NG];
__device__ float g_decWihsT[3*KSZ];
__device__ float g_decWhhT[3*KSZ];
__device__ float g_WcPack[512*NG];
__device__ float g_decWeT[EE*NG];
__device__ float g_biasDec[4*NG];
__device__ float g_dech[4*BB*HH];
__device__ float g_decc[4*BB*HH];
__device__ float g_attn[BB*HH];
__device__ float g_cin[BB*512];
__device__ float g_const[4*BB*NG];
__device__ float g_h1[NT*BB*HH];
__device__ float g_h2[NT*BB*HH];
__device__ unsigned g_bcnt = 0;
__device__ unsigned g_bsense = 0;

__device__ __forceinline__ float sigmoidf(float x){ return 1.f/(1.f + expf(-x)); }

// sense-reversing grid barrier; EVEN uses per launch so g_bsense ends at 0
__device__ __forceinline__ void grid_barrier(unsigned nb, unsigned& sense)
{
    __syncthreads();
    if (threadIdx.x == 0){
        unsigned want = sense ^ 1u;
        __threadfence();
        if (atomicAdd(&g_bcnt, 1u) == nb - 1u){
            atomicExch(&g_bcnt, 0u);
            __threadfence();
            atomicExch(&g_bsense, want);
        } else {
            while (atomicAdd(&g_bsense, 0u) != want) __nanosleep(64);
        }
        __threadfence();
    }
    __syncthreads();
    sense ^= 1u;
}

__global__ void transpose_k(const float* __restrict__ src, int ldS, int rows, int cols,
                            float* __restrict__ dst, int ldD)
{
    __shared__ float tile[32][33];
    int c0 = blockIdx.x*32, r0 = blockIdx.y*32;
    for (int i = threadIdx.y; i < 32; i += 8){
        int r = r0 + i, c = c0 + threadIdx.x;
        tile[i][threadIdx.x] = (r < rows && c < cols) ? src[(size_t)r*ldS + c] : 0.f;
    }
    __syncthreads();
    for (int i = threadIdx.y; i < 32; i += 8){
        int c = c0 + i, r = r0 + threadIdx.x;
        if (c < cols && r < rows) dst[(size_t)c*ldD + r] = tile[threadIdx.x][i];
    }
}

__global__ void addv_k(const float* a, const float* b, float* o, int n)
{
    int i = blockIdx.x*256 + threadIdx.x;
    if (i < n) o[i] = a[i] + b[i];
}

__global__ void emb_k(const float* __restrict__ x, const float* __restrict__ W,
                      const float* __restrict__ bias, float* __restrict__ emb)
{
    int m = blockIdx.x;
    int t = m / GT; int rem = m % GT; int g = rem >> 6; int b = rem & 63;
    const float* xr = x + (((size_t)(b*TT_ + t))*GG + g)*FF;
    int e = threadIdx.x;
    float v = bias[e] + xr[0]*W[e*4] + xr[1]*W[e*4+1] + xr[2]*W[e*4+2] + xr[3]*W[e*4+3];
    emb[(size_t)m*EE + e] = fmaxf(v, 0.f);
}

// C = A(MxK) @ B(KxN) + bias, 128x128 tile, BK=8
__global__ void gemm_k(const float* __restrict__ A, const float* __restrict__ B,
                       const float* __restrict__ bias, float* __restrict__ C,
                       int M, int N, int K)
{
    __shared__ float As[8][128];
    __shared__ float Bs[8][128];
    int tid = threadIdx.x;
    int m0 = blockIdx.y*128, n0 = blockIdx.x*128;
    int tx = tid & 15, ty = tid >> 4;
    float acc[8][8];
    #pragma unroll
    for (int i = 0; i < 8; i++)
        #pragma unroll
        for (int j = 0; j < 8; j++) acc[i][j] = 0.f;
    int arow = tid >> 1, acol = (tid & 1)*4;
    int brow = tid >> 5, bcol = (tid & 31)*4;
    for (int k0 = 0; k0 < K; k0 += 8){
        float4 av = make_float4(0.f,0.f,0.f,0.f);
        int gm = m0 + arow;
        if (gm < M) av = *reinterpret_cast<const float4*>(A + (size_t)gm*K + k0 + acol);
        As[acol+0][arow] = av.x; As[acol+1][arow] = av.y;
        As[acol+2][arow] = av.z; As[acol+3][arow] = av.w;
        *reinterpret_cast<float4*>(&Bs[brow][bcol]) =
            *reinterpret_cast<const float4*>(B + (size_t)(k0+brow)*N + n0 + bcol);
        __syncthreads();
        #pragma unroll
        for (int kk = 0; kk < 8; kk++){
            float a[8], b[8];
            *reinterpret_cast<float4*>(a)   = *reinterpret_cast<float4*>(&As[kk][ty*4]);
            *reinterpret_cast<float4*>(a+4) = *reinterpret_cast<float4*>(&As[kk][64+ty*4]);
            *reinterpret_cast<float4*>(b)   = *reinterpret_cast<float4*>(&Bs[kk][tx*4]);
            *reinterpret_cast<float4*>(b+4) = *reinterpret_cast<float4*>(&Bs[kk][64+tx*4]);
            #pragma unroll
            for (int i = 0; i < 8; i++)
                #pragma unroll
                for (int j = 0; j < 8; j++) acc[i][j] += a[i]*b[j];
        }
        __syncthreads();
    }
    #pragma unroll
    for (int i = 0; i < 8; i++){
        int gm = m0 + ((i < 4) ? (ty*4 + i) : (64 + ty*4 + (i-4)));
        if (gm >= M) continue;
        #pragma unroll
        for (int j = 0; j < 8; j++){
            int gn = n0 + ((j < 4) ? (tx*4 + j) : (64 + tx*4 + (j-4)));
            C[(size_t)gm*N + gn] = acc[i][j] + bias[gn];
        }
    }
}

// Persistent encoder layer: 64 timesteps, one launch. 352 blocks x 128 thr.
// Block = 16 rows x 32 h-cols; cell state in registers across all steps.
__global__ __launch_bounds__(128, 3) void enc_layer_k(
    const float* __restrict__ X, const float* __restrict__ WhhT,
    float* __restrict__ Y, float* __restrict__ Cfin)
{
    __shared__ float sH[16][33];
    __shared__ float sW[32][4][32];
    const int tid = threadIdx.x;
    const int tx = tid & 31, ty = tid >> 5;
    const int m0 = (blockIdx.x >> 3)*16, j0 = (blockIdx.x & 7)*32;
    const unsigned nb = gridDim.x;
    unsigned sense = 0;
    float c[4] = {0.f,0.f,0.f,0.f};
    const int j = j0 + tx;
    for (int t = 0; t < 64; t++){
        float acc[4][4];
        #pragma unroll
        for (int i = 0; i < 4; i++){ acc[i][0]=0.f; acc[i][1]=0.f; acc[i][2]=0.f; acc[i][3]=0.f; }
        if (t > 0){
            const float* Hp = Y + (size_t)(t-1)*GT*HH;
            for (int k0 = 0; k0 < HH; k0 += 32){
                {
                    int r = tid >> 3, kc = (tid & 7)*4;
                    float4 v = __ldcg(reinterpret_cast<const float4*>(Hp + (size_t)(m0+r)*HH + k0 + kc));
                    sH[r][kc] = v.x; sH[r][kc+1] = v.y; sH[r][kc+2] = v.z; sH[r][kc+3] = v.w;
                }
                #pragma unroll
                for (int q = 0; q < 32; q++){
                    int lin = q*128 + tid;
                    int kr = lin >> 7, col = lin & 127;
                    sW[kr][col >> 5][col & 31] =
                        WhhT[(size_t)(k0+kr)*NG + (col >> 5)*HH + j0 + (col & 31)];
                }
                __syncthreads();
                #pragma unroll
                for (int kk = 0; kk < 32; kk++){
                    float w0 = sW[kk][0][tx], w1 = sW[kk][1][tx];
                    float w2 = sW[kk][2][tx], w3 = sW[kk][3][tx];
                    #pragma unroll
                    for (int mi = 0; mi < 4; mi++){
                        float a = sH[ty + mi*4][kk];
                        acc[mi][0] += a*w0; acc[mi][1] += a*w1;
                        acc[mi][2] += a*w2; acc[mi][3] += a*w3;
                    }
                }
                __syncthreads();
            }
        }
        const float* xp = X + (size_t)t*GT*NG;
        float* yp = Y + (size_t)t*GT*HH;
        #pragma unroll
        for (int mi = 0; mi < 4; mi++){
            int m = m0 + ty + mi*4;
            const float* cp = xp + (size_t)m*NG;
            float gi = acc[mi][0] + cp[j];
            float gf = acc[mi][1] + cp[HH + j];
            float gg = acc[mi][2] + cp[2*HH + j];
            float go = acc[mi][3] + cp[3*HH + j];
            c[mi] = sigmoidf(gf)*c[mi] + sigmoidf(gi)*tanhf(gg);
            yp[(size_t)m*HH + j] = sigmoidf(go)*tanhf(c[mi]);
        }
        grid_barrier(nb, sense);
    }
    #pragma unroll
    for (int mi = 0; mi < 4; mi++)
        Cfin[(size_t)(m0 + ty + mi*4)*HH + j] = c[mi];
}

__global__ void snap_k(const float* __restrict__ Yt, const float* __restrict__ C,
                       const int* __restrict__ tord, float* dh, float* dc)
{
    int b = blockIdx.x, h = threadIdx.x;
    int row = (*tord)*64 + b;
    dh[b*HH + h] = Yt[(size_t)row*HH + h];
    dc[b*HH + h] = C[(size_t)row*HH + h];
}

// attention: hq.wa_h + attn_b per-b constant -> cancels in softmax
__global__ void attn_k(const float* __restrict__ Y3, const float* __restrict__ attnW,
                       float* __restrict__ attn)
{
    int b = blockIdx.x, tid = threadIdx.x;
    __shared__ float wae[HH];
    __shared__ float sc[GT];
    __shared__ float red[256];
    wae[tid] = attnW[HH + tid];
    __syncthreads();
    for (int idx = tid; idx < GT; idx += 256){
        int g = idx % GG, t = idx / GG;
        const float* row = Y3 + ((size_t)(t*GT + g*64 + b))*HH;
        float s = 0.f;
        #pragma unroll 4
        for (int h = 0; h < HH; h++) s += row[h]*wae[h];
        sc[idx] = s;
    }
    __syncthreads();
    float mx = -1e30f;
    for (int idx = tid; idx < GT; idx += 256) mx = fmaxf(mx, sc[idx]);
    red[tid] = mx; __syncthreads();
    for (int s = 128; s > 0; s >>= 1){ if (tid < s) red[tid] = fmaxf(red[tid], red[tid+s]); __syncthreads(); }
    mx = red[0]; __syncthreads();
    float sm = 0.f;
    for (int idx = tid; idx < GT; idx += 256){ float e = expf(sc[idx]-mx); sc[idx] = e; sm += e; }
    red[tid] = sm; __syncthreads();
    for (int s = 128; s > 0; s >>= 1){ if (tid < s) red[tid] += red[tid+s]; __syncthreads(); }
    float inv = 1.f/red[0];
    __syncthreads();
    float a0 = 0.f;
    for (int idx = 0; idx < GT; idx++){
        int g = idx % GG, t = idx / GG;
        a0 += sc[idx]*Y3[((size_t)(t*GT + g*64 + b))*HH + tid];
    }
    attn[b*HH + tid] = a0*inv;
}

__global__ void pack_cin_k(const float* dh0, const float* attn, float* cin)
{
    int b = blockIdx.x, k = threadIdx.x;
    cin[b*512 + k] = (k < HH) ? dh0[b*HH + k] : attn[b*HH + (k - HH)];
}

// Persistent decoder: 64 steps x 4 layers, one launch. 192 blocks x 128 thr.
// Block = 8 rows x 32 h-cols. Out-proj + next-emb computed per row-block.
__global__ __launch_bounds__(128, 2) void dec_persist_k(
    const float* __restrict__ x, const int* __restrict__ tord,
    const float* __restrict__ cnst, const float* __restrict__ cinAll,
    const float* __restrict__ WeT, const float* __restrict__ WihsT,
    float* __restrict__ H1, float* __restrict__ H2,
    const float* __restrict__ outW, const float* __restrict__ outB,
    const float* __restrict__ Wemb, const float* __restrict__ bemb,
    float* __restrict__ dout)
{
    __shared__ float sE[8][128];
    __shared__ float sIn[8][33];
    __shared__ float sW[32][4][32];
    __shared__ float sRed[8][16];
    __shared__ float sOut[8][4];
    const int tid = threadIdx.x;
    const int tx = tid & 31, ty = tid >> 5;
    const int jc = blockIdx.x & 7;
    const int m0 = (blockIdx.x >> 3)*8, j0 = jc*32;
    const unsigned nb = gridDim.x;
    unsigned sense = 0;
    const int tordv = *tord;
    const int j = j0 + tx;
    for (int t = 0; t < 64; t++){
        if (t == 0){
            for (int idx = tid; idx < 8*128; idx += 128){
                int rr = idx >> 7, e = idx & 127;
                int m = m0 + rr;
                const float* xr = x + (((size_t)((m & 63)*TT_ + 63))*GG + (tordv + (m >> 6)))*FF;
                float v = bemb[e] + xr[0]*Wemb[e*4] + xr[1]*Wemb[e*4+1]
                                  + xr[2]*Wemb[e*4+2] + xr[3]*Wemb[e*4+3];
                sE[rr][e] = fmaxf(v, 0.f);
            }
            __syncthreads();
        } else {
            {
                int r = tid >> 4, sub = tid & 15, o = sub & 3, seg = sub >> 2;
                const float* hrow = H2 + (size_t)(m0 + r)*HH;
                float s = 0.f;
                #pragma unroll 4
                for (int h = seg*64; h < seg*64 + 64; h++)
                    s += __ldcg(hrow + h) * outW[o*HH + h];
                sRed[r][sub] = s;
            }
            __syncthreads();
            if (tid < 32){
                int rr = tid >> 2, oo = tid & 3;
                float v = sRed[rr][oo] + sRed[rr][4+oo] + sRed[rr][8+oo] + sRed[rr][12+oo] + outB[oo];
                sOut[rr][oo] = v;
                if (jc == 0){
                    int m = m0 + rr;
                    dout[(size_t)(m & 63)*(TT_*NT*FF) + (size_t)(t-1)*(NT*FF) + (m >> 6)*FF + oo] = v;
                }
            }
            __syncthreads();
            for (int idx = tid; idx < 8*128; idx += 128){
                int rr = idx >> 7, e = idx & 127;
                float v = bemb[e] + sOut[rr][0]*Wemb[e*4] + sOut[rr][1]*Wemb[e*4+1]
                        + sOut[rr][2]*Wemb[e*4+2] + sOut[rr][3]*Wemb[e*4+3];
                sE[rr][e] = fmaxf(v, 0.f);
            }
            __syncthreads();
        }
        for (int l = 0; l < 4; l++){
            float acc[2][4] = {{0.f,0.f,0.f,0.f},{0.f,0.f,0.f,0.f}};
            const float* Wt = (l == 0) ? WeT : (WihsT + (size_t)(l-1)*KSZ);
            const int K = (l == 0) ? EE : HH;
            const float* In = (l == 2) ? H2 : H1;
            float* Ho = (l == 0 || l == 2) ? H1 : H2;
            for (int k0 = 0; k0 < K; k0 += 32){
                if (l > 0 && tid < 64){
                    int r = tid >> 3, kc = (tid & 7)*4;
                    float4 v = __ldcg(reinterpret_cast<const float4*>(In + (size_t)(m0+r)*HH + k0 + kc));
                    sIn[r][kc] = v.x; sIn[r][kc+1] = v.y; sIn[r][kc+2] = v.z; sIn[r][kc+3] = v.w;
                }
                #pragma unroll
                for (int q = 0; q < 32; q++){
                    int lin = q*128 + tid;
                    int kr = lin >> 7, col = lin & 127;
                    sW[kr][col >> 5][col & 31] =
                        Wt[(size_t)(k0+kr)*NG + (col >> 5)*HH + j0 + (col & 31)];
                }
                __syncthreads();
                #pragma unroll
                for (int kk = 0; kk < 32; kk++){
                    float w0 = sW[kk][0][tx], w1 = sW[kk][1][tx];
                    float w2 = sW[kk][2][tx], w3 = sW[kk][3][tx];
                    float a0 = (l == 0) ? sE[ty*2][k0+kk]   : sIn[ty*2][kk];
                    float a1 = (l == 0) ? sE[ty*2+1][k0+kk] : sIn[ty*2+1][kk];
                    acc[0][0]+=a0*w0; acc[0][1]+=a0*w1; acc[0][2]+=a0*w2; acc[0][3]+=a0*w3;
                    acc[1][0]+=a1*w0; acc[1][1]+=a1*w1; acc[1][2]+=a1*w2; acc[1][3]+=a1*w3;
                }
                __syncthreads();
            }
            const float* cl = cnst + (size_t)l*BB*NG;
            const float* ci = cinAll + (size_t)l*BB*HH;
            #pragma unroll
            for (int rr = 0; rr < 2; rr++){
                int m = m0 + ty*2 + rr, b = m & 63;
                const float* cp = cl + (size_t)b*NG;
                float gi = acc[rr][0] + cp[j];
                float gf = acc[rr][1] + cp[HH + j];
                float gg = acc[rr][2] + cp[2*HH + j];
                float go = acc[rr][3] + cp[3*HH + j];
                float c2 = sigmoidf(gf)*ci[b*HH + j] + sigmoidf(gi)*tanhf(gg);
                Ho[(size_t)m*HH + j] = sigmoidf(go)*tanhf(c2);
            }
            grid_barrier(nb, sense);
        }
    }
    {
        int r = tid >> 4, sub = tid & 15, o = sub & 3, seg = sub >> 2;
        const float* hrow = H2 + (size_t)(m0 + r)*HH;
        float s = 0.f;
        #pragma unroll 4
        for (int h = seg*64; h < seg*64 + 64; h++)
            s += __ldcg(hrow + h) * outW[o*HH + h];
        sRed[r][sub] = s;
    }
    __syncthreads();
    if (tid < 32 && jc == 0){
        int rr = tid >> 2, oo = tid & 3;
        float v = sRed[rr][oo] + sRed[rr][4+oo] + sRed[rr][8+oo] + sRed[rr][12+oo] + outB[oo];
        int m = m0 + rr;
        dout[(size_t)(m & 63)*(TT_*NT*FF) + 63u*(NT*FF) + (m >> 6)*FF + oo] = v;
    }
}

static float* symaddr(const void* sym)
{
    void* p = nullptr;
    cudaGetSymbolAddress(&p, sym);
    return (float*)p;
}

extern "C" void kernel_launch(void* const* d_in, const int* in_sizes, int n_in,
                              void* d_out, int out_size)
{
    (void)in_sizes; (void)n_in; (void)out_size;
    const float* x       = (const float*)d_in[0];
    const float* encLinW = (const float*)d_in[2];
    const float* encLinB = (const float*)d_in[3];
    const float* encWih0 = (const float*)d_in[4];
    const float* encWihs = (const float*)d_in[5];
    const float* encWhh  = (const float*)d_in[6];
    const float* encBih  = (const float*)d_in[7];
    const float* encBhh  = (const float*)d_in[8];
    const float* decEmbW = (const float*)d_in[9];
    const float* decEmbB = (const float*)d_in[10];
    const float* attnW   = (const float*)d_in[11];
    const float* decWih0 = (const float*)d_in[13];
    const float* decWihs = (const float*)d_in[14];
    const float* decWhh  = (const float*)d_in[15];
    const float* decBih  = (const float*)d_in[16];
    const float* decBhh  = (const float*)d_in[17];
    const float* outW    = (const float*)d_in[18];
    const float* outB    = (const float*)d_in[19];
    const int*   tord    = (const int*)d_in[20];
    float* out = (float*)d_out;

    float* pEmb = symaddr(g_emb);       float* pX = symaddr(g_X);
    float* pY0 = symaddr(g_Y0);         float* pY1 = symaddr(g_Y1);
    float* pC = symaddr(g_Cst);         float* pWih0T = symaddr(g_encWih0T);
    float* pWihsT = symaddr(g_encWihsT);float* pWhhT = symaddr(g_encWhhT);
    float* pBiasEnc = symaddr(g_biasEnc);
    float* pDecWihsT = symaddr(g_decWihsT);
    float* pDecWhhT = symaddr(g_decWhhT);
    float* pPack = symaddr(g_WcPack);   float* pWeT = symaddr(g_decWeT);
    float* pBiasDec = symaddr(g_biasDec);
    float* pDech = symaddr(g_dech);     float* pDecc = symaddr(g_decc);
    float* pAttn = symaddr(g_attn);     float* pCin = symaddr(g_cin);
    float* pConst = symaddr(g_const);
    float* pH1 = symaddr(g_h1);         float* pH2 = symaddr(g_h2);

    dim3 tb(32, 8);
    transpose_k<<<dim3(4, 32), tb>>>(encWih0, EE, NG, EE, pWih0T, NG);
    for (int l = 0; l < 3; l++)
        transpose_k<<<dim3(8, 32), tb>>>(encWihs + (size_t)l*NG*HH, HH, NG, HH, pWihsT + (size_t)l*KSZ, NG);
    for (int l = 0; l < 4; l++)
        transpose_k<<<dim3(8, 32), tb>>>(encWhh + (size_t)l*NG*HH, HH, NG, HH, pWhhT + (size_t)l*KSZ, NG);
    addv_k<<<16, 256>>>(encBih, encBhh, pBiasEnc, 4*NG);
    for (int l = 0; l < 3; l++)
        transpose_k<<<dim3(8, 32), tb>>>(decWihs + (size_t)l*NG*HH, HH, NG, HH, pDecWihsT + (size_t)l*KSZ, NG);
    for (int l = 1; l < 4; l++)
        transpose_k<<<dim3(8, 32), tb>>>(decWhh + (size_t)l*NG*HH, HH, NG, HH, pDecWhhT + (size_t)(l-1)*KSZ, NG);
    transpose_k<<<dim3(8, 32), tb>>>(decWhh, HH, NG, HH, pPack, NG);
    transpose_k<<<dim3(8, 32), tb>>>(decWih0, 384, NG, HH, pPack + (size_t)HH*NG, NG);
    transpose_k<<<dim3(4, 32), tb>>>(decWih0 + HH, 384, NG, EE, pWeT, NG);
    addv_k<<<16, 256>>>(decBih, decBhh, pBiasDec, 4*NG);

    emb_k<<<MTOT, 128>>>(x, encLinW, encLinB, pEmb);

    const float* Ain = pEmb;
    int Kin = EE;
    const float* WT = pWih0T;
    float* Ybuf[2] = { pY0, pY1 };
    for (int l = 0; l < 4; l++){
        gemm_k<<<dim3(8, MTOT/128), 256>>>(Ain, WT, pBiasEnc + l*NG, pX, MTOT, NG, Kin);
        float* Yc = Ybuf[l & 1];
        enc_layer_k<<<352, 128>>>(pX, pWhhT + (size_t)l*KSZ, Yc, pC);
        snap_k<<<64, 256>>>(Yc + (size_t)(TT_-1)*GT*HH, pC, tord,
                            pDech + (size_t)l*BB*HH, pDecc + (size_t)l*BB*HH);
        Ain = Yc; Kin = HH; WT = pWihsT + (size_t)l*KSZ;
    }
    float* Ytop = pY1;

    attn_k<<<BB, 256>>>(Ytop, attnW, pAttn);
    pack_cin_k<<<BB, 512>>>(pDech, pAttn, pCin);
    gemm_k<<<dim3(8, 1), 256>>>(pCin, pPack, pBiasDec, pConst, BB, NG, 512);
    for (int l = 1; l < 4; l++)
        gemm_k<<<dim3(8, 1), 256>>>(pDech + (size_t)l*BB*HH, pDecWhhT + (size_t)(l-1)*KSZ,
                                    pBiasDec + l*NG, pConst + (size_t)l*BB*NG, BB, NG, HH);

    dec_persist_k<<<192, 128>>>(x, tord, pConst, pDecc, pWeT, pDecWihsT,
                                pH1, pH2, outW, outB, decEmbW, decEmbB, out);
}

// round 6
// speedup vs baseline: 1.3057x; 1.0905x over previous
#include <cuda_runtime.h>
#include <cuda_bf16.h>
#include <cstdint>

#define BB   64
#define TT_  64
#define GG   11
#define FF   4
#define HH   256
#define EE   128
#define NT   3
#define GT   (GG*BB)     // 704
#define MTOT (TT_*GT)    // 45056
#define NG   1024
#define KSZ  (256*1024)

__device__ float g_X[MTOT*NG];
__device__ float g_Y0[MTOT*HH];
__device__ float g_Y1[MTOT*HH];
__device__ float g_Cst[GT*HH];
__device__ __nv_bfloat16 g_Ahi[MTOT*HH];
__device__ __nv_bfloat16 g_Alo[MTOT*HH];
__device__ __nv_bfloat16 g_Whi[(EE + 3*HH)*NG];
__device__ __nv_bfloat16 g_Wlo[(EE + 3*HH)*NG];
__device__ float g_encWhhT[4*KSZ];
__device__ float g_biasEnc[4*NG];
__device__ float g_decWihsT[3*KSZ];
__device__ float g_decWhhT[3*KSZ];
__device__ float g_WcPack[512*NG];
__device__ float g_decWeT[EE*NG];
__device__ float g_biasDec[4*NG];
__device__ float g_dech[4*BB*HH];
__device__ float g_decc[4*BB*HH];
__device__ float g_attn[BB*HH];
__device__ float g_cin[BB*512];
__device__ float g_const[4*BB*NG];
__device__ float g_h1[NT*BB*HH];
__device__ float g_h2[NT*BB*HH];
__device__ unsigned g_bcnt = 0;
__device__ unsigned g_bsense = 0;

__device__ __forceinline__ float sigmoidf(float x){ return 1.f/(1.f + expf(-x)); }

__device__ __forceinline__ void grid_barrier(unsigned nb, unsigned& sense)
{
    __syncthreads();
    if (threadIdx.x == 0){
        unsigned want = sense ^ 1u;
        __threadfence();
        if (atomicAdd(&g_bcnt, 1u) == nb - 1u){
            atomicExch(&g_bcnt, 0u);
            __threadfence();
            atomicExch(&g_bsense, want);
        } else {
            while (atomicAdd(&g_bsense, 0u) != want) __nanosleep(64);
        }
        __threadfence();
    }
    __syncthreads();
    sense ^= 1u;
}

__global__ void transpose_k(const float* __restrict__ src, int ldS, int rows, int cols,
                            float* __restrict__ dst, int ldD)
{
    __shared__ float tile[32][33];
    int c0 = blockIdx.x*32, r0 = blockIdx.y*32;
    for (int i = threadIdx.y; i < 32; i += 8){
        int r = r0 + i, c = c0 + threadIdx.x;
        tile[i][threadIdx.x] = (r < rows && c < cols) ? src[(size_t)r*ldS + c] : 0.f;
    }
    __syncthreads();
    for (int i = threadIdx.y; i < 32; i += 8){
        int c = c0 + i, r = r0 + threadIdx.x;
        if (c < cols && r < rows) dst[(size_t)c*ldD + r] = tile[threadIdx.x][i];
    }
}

__global__ void addv_k(const float* a, const float* b, float* o, int n)
{
    int i = blockIdx.x*256 + threadIdx.x;
    if (i < n) o[i] = a[i] + b[i];
}

// fp32 -> bf16 hi/lo split
__global__ void wsplit_k(const float* __restrict__ src, __nv_bfloat16* __restrict__ hi,
                         __nv_bfloat16* __restrict__ lo, int n)
{
    int i = blockIdx.x*256 + threadIdx.x;
    if (i < n){
        float v = src[i];
        __nv_bfloat16 h = __float2bfloat16(v);
        hi[i] = h;
        lo[i] = __float2bfloat16(v - __bfloat162float(h));
    }
}

// emb (bf16 hi/lo only): m = t*704 + g*64 + b
__global__ void emb_k(const float* __restrict__ x, const float* __restrict__ W,
                      const float* __restrict__ bias,
                      __nv_bfloat16* __restrict__ hi, __nv_bfloat16* __restrict__ lo)
{
    int m = blockIdx.x;
    int t = m / GT; int rem = m % GT; int g = rem >> 6; int b = rem & 63;
    const float* xr = x + (((size_t)(b*TT_ + t))*GG + g)*FF;
    int e = threadIdx.x;
    float v = bias[e] + xr[0]*W[e*4] + xr[1]*W[e*4+1] + xr[2]*W[e*4+2] + xr[3]*W[e*4+3];
    v = fmaxf(v, 0.f);
    __nv_bfloat16 h = __float2bfloat16(v);
    hi[(size_t)m*EE + e] = h;
    lo[(size_t)m*EE + e] = __float2bfloat16(v - __bfloat162float(h));
}

__device__ __forceinline__ void mma_bf16(float* c, const uint32_t* a, uint32_t b0, uint32_t b1)
{
    asm volatile("mma.sync.aligned.m16n8k16.row.col.f32.bf16.bf16.f32 "
        "{%0,%1,%2,%3}, {%4,%5,%6,%7}, {%8,%9}, {%0,%1,%2,%3};"
        : "+f"(c[0]), "+f"(c[1]), "+f"(c[2]), "+f"(c[3])
        : "r"(a[0]), "r"(a[1]), "r"(a[2]), "r"(a[3]), "r"(b0), "r"(b1));
}

// Tensor-core split-bf16 GEMM: C[M][1024] = A[M][K] @ W[1024][K]^T + bias
// A,W given as bf16 hi/lo pairs. 128x128 tile, BK=32, 8 warps.
__global__ __launch_bounds__(256, 2) void gemm_tc_k(
    const __nv_bfloat16* __restrict__ Ahi, const __nv_bfloat16* __restrict__ Alo,
    const __nv_bfloat16* __restrict__ Whi, const __nv_bfloat16* __restrict__ Wlo,
    const float* __restrict__ bias, float* __restrict__ C, int K)
{
    __shared__ __align__(16) uint32_t sA[2][128][20];
    __shared__ __align__(16) uint32_t sB[2][128][20];
    const int tid = threadIdx.x;
    const int lane = tid & 31, wid = tid >> 5;
    const int wm = wid & 3, wn = wid >> 2;        // 4 m-warps x 2 n-warps
    const int m0 = blockIdx.y*128, n0 = blockIdx.x*128;
    const int g = lane >> 2, q = lane & 3;
    float acc[2][8][4];
    #pragma unroll
    for (int i = 0; i < 2; i++)
        #pragma unroll
        for (int j = 0; j < 8; j++){ acc[i][j][0]=0.f; acc[i][j][1]=0.f; acc[i][j][2]=0.f; acc[i][j][3]=0.f; }

    for (int k0 = 0; k0 < K; k0 += 32){
        #pragma unroll
        for (int rep = 0; rep < 2; rep++){
            int chunk = tid + rep*256;
            int row = chunk >> 2, off = chunk & 3;
            size_t ga = (size_t)(m0 + row)*K + k0 + off*8;
            size_t gb = (size_t)(n0 + row)*K + k0 + off*8;
            *reinterpret_cast<uint4*>(&sA[0][row][off*4]) = *reinterpret_cast<const uint4*>(Ahi + ga);
            *reinterpret_cast<uint4*>(&sA[1][row][off*4]) = *reinterpret_cast<const uint4*>(Alo + ga);
            *reinterpret_cast<uint4*>(&sB[0][row][off*4]) = *reinterpret_cast<const uint4*>(Whi + gb);
            *reinterpret_cast<uint4*>(&sB[1][row][off*4]) = *reinterpret_cast<const uint4*>(Wlo + gb);
        }
        __syncthreads();
        #pragma unroll
        for (int ks = 0; ks < 2; ks++){
            int kp = q + ks*8;
            uint32_t a[2][2][4];
            #pragma unroll
            for (int fm = 0; fm < 2; fm++){
                int row = wm*32 + fm*16;
                #pragma unroll
                for (int s = 0; s < 2; s++){
                    a[fm][s][0] = sA[s][row+g][kp];
                    a[fm][s][1] = sA[s][row+g+8][kp];
                    a[fm][s][2] = sA[s][row+g][kp+4];
                    a[fm][s][3] = sA[s][row+g+8][kp+4];
                }
            }
            #pragma unroll
            for (int fn = 0; fn < 8; fn++){
                int nr = wn*64 + fn*8 + g;
                uint32_t bh0 = sB[0][nr][kp], bh1 = sB[0][nr][kp+4];
                uint32_t bl0 = sB[1][nr][kp], bl1 = sB[1][nr][kp+4];
                #pragma unroll
                for (int fm = 0; fm < 2; fm++){
                    mma_bf16(acc[fm][fn], a[fm][0], bh0, bh1);   // hi*hi
                    mma_bf16(acc[fm][fn], a[fm][0], bl0, bl1);   // hi*lo
                    mma_bf16(acc[fm][fn], a[fm][1], bh0, bh1);   // lo*hi
                }
            }
        }
        __syncthreads();
    }
    #pragma unroll
    for (int fm = 0; fm < 2; fm++){
        int r = m0 + wm*32 + fm*16 + g;
        #pragma unroll
        for (int fn = 0; fn < 8; fn++){
            int cn = n0 + wn*64 + fn*8 + q*2;
            float b0 = bias[cn], b1 = bias[cn+1];
            float2 v0 = make_float2(acc[fm][fn][0] + b0, acc[fm][fn][1] + b1);
            float2 v1 = make_float2(acc[fm][fn][2] + b0, acc[fm][fn][3] + b1);
            *reinterpret_cast<float2*>(C + (size_t)r*NG + cn) = v0;
            *reinterpret_cast<float2*>(C + (size_t)(r+8)*NG + cn) = v1;
        }
    }
}

// fp32 fallback GEMM (decoder constants): C = A(MxK)@B(KxN)+bias
__global__ void gemm_k(const float* __restrict__ A, const float* __restrict__ B,
                       const float* __restrict__ bias, float* __restrict__ C,
                       int M, int N, int K)
{
    __shared__ float As[8][128];
    __shared__ float Bs[8][128];
    int tid = threadIdx.x;
    int m0 = blockIdx.y*128, n0 = blockIdx.x*128;
    int tx = tid & 15, ty = tid >> 4;
    float acc[8][8];
    #pragma unroll
    for (int i = 0; i < 8; i++)
        #pragma unroll
        for (int j = 0; j < 8; j++) acc[i][j] = 0.f;
    int arow = tid >> 1, acol = (tid & 1)*4;
    int brow = tid >> 5, bcol = (tid & 31)*4;
    for (int k0 = 0; k0 < K; k0 += 8){
        float4 av = make_float4(0.f,0.f,0.f,0.f);
        int gm = m0 + arow;
        if (gm < M) av = *reinterpret_cast<const float4*>(A + (size_t)gm*K + k0 + acol);
        As[acol+0][arow] = av.x; As[acol+1][arow] = av.y;
        As[acol+2][arow] = av.z; As[acol+3][arow] = av.w;
        *reinterpret_cast<float4*>(&Bs[brow][bcol]) =
            *reinterpret_cast<const float4*>(B + (size_t)(k0+brow)*N + n0 + bcol);
        __syncthreads();
        #pragma unroll
        for (int kk = 0; kk < 8; kk++){
            float a[8], b[8];
            *reinterpret_cast<float4*>(a)   = *reinterpret_cast<float4*>(&As[kk][ty*4]);
            *reinterpret_cast<float4*>(a+4) = *reinterpret_cast<float4*>(&As[kk][64+ty*4]);
            *reinterpret_cast<float4*>(b)   = *reinterpret_cast<float4*>(&Bs[kk][tx*4]);
            *reinterpret_cast<float4*>(b+4) = *reinterpret_cast<float4*>(&Bs[kk][64+tx*4]);
            #pragma unroll
            for (int i = 0; i < 8; i++)
                #pragma unroll
                for (int j = 0; j < 8; j++) acc[i][j] += a[i]*b[j];
        }
        __syncthreads();
    }
    #pragma unroll
    for (int i = 0; i < 8; i++){
        int gm = m0 + ((i < 4) ? (ty*4 + i) : (64 + ty*4 + (i-4)));
        if (gm >= M) continue;
        #pragma unroll
        for (int j = 0; j < 8; j++){
            int gn = n0 + ((j < 4) ? (tx*4 + j) : (64 + tx*4 + (j-4)));
            C[(size_t)gm*N + gn] = acc[i][j] + bias[gn];
        }
    }
}

// Persistent encoder layer: 64 timesteps, one launch. Also emits h as bf16 hi/lo.
__global__ __launch_bounds__(128, 3) void enc_layer_k(
    const float* __restrict__ X, const float* __restrict__ WhhT,
    float* __restrict__ Y, float* __restrict__ Cfin,
    __nv_bfloat16* __restrict__ Yhi, __nv_bfloat16* __restrict__ Ylo)
{
    __shared__ float sH[16][33];
    __shared__ float sW[32][4][32];
    const int tid = threadIdx.x;
    const int tx = tid & 31, ty = tid >> 5;
    const int m0 = (blockIdx.x >> 3)*16, j0 = (blockIdx.x & 7)*32;
    const unsigned nb = gridDim.x;
    unsigned sense = 0;
    float c[4] = {0.f,0.f,0.f,0.f};
    const int j = j0 + tx;
    for (int t = 0; t < 64; t++){
        float acc[4][4];
        #pragma unroll
        for (int i = 0; i < 4; i++){ acc[i][0]=0.f; acc[i][1]=0.f; acc[i][2]=0.f; acc[i][3]=0.f; }
        if (t > 0){
            const float* Hp = Y + (size_t)(t-1)*GT*HH;
            for (int k0 = 0; k0 < HH; k0 += 32){
                {
                    int r = tid >> 3, kc = (tid & 7)*4;
                    float4 v = __ldcg(reinterpret_cast<const float4*>(Hp + (size_t)(m0+r)*HH + k0 + kc));
                    sH[r][kc] = v.x; sH[r][kc+1] = v.y; sH[r][kc+2] = v.z; sH[r][kc+3] = v.w;
                }
                #pragma unroll
                for (int qq = 0; qq < 32; qq++){
                    int lin = qq*128 + tid;
                    int kr = lin >> 7, col = lin & 127;
                    sW[kr][col >> 5][col & 31] =
                        WhhT[(size_t)(k0+kr)*NG + (col >> 5)*HH + j0 + (col & 31)];
                }
                __syncthreads();
                #pragma unroll
                for (int kk = 0; kk < 32; kk++){
                    float w0 = sW[kk][0][tx], w1 = sW[kk][1][tx];
                    float w2 = sW[kk][2][tx], w3 = sW[kk][3][tx];
                    #pragma unroll
                    for (int mi = 0; mi < 4; mi++){
                        float a = sH[ty + mi*4][kk];
                        acc[mi][0] += a*w0; acc[mi][1] += a*w1;
                        acc[mi][2] += a*w2; acc[mi][3] += a*w3;
                    }
                }
                __syncthreads();
            }
        }
        const float* xp = X + (size_t)t*GT*NG;
        #pragma unroll
        for (int mi = 0; mi < 4; mi++){
            int m = m0 + ty + mi*4;
            const float* cp = xp + (size_t)m*NG;
            float gi = acc[mi][0] + cp[j];
            float gf = acc[mi][1] + cp[HH + j];
            float gg = acc[mi][2] + cp[2*HH + j];
            float go = acc[mi][3] + cp[3*HH + j];
            c[mi] = sigmoidf(gf)*c[mi] + sigmoidf(gi)*tanhf(gg);
            float h = sigmoidf(go)*tanhf(c[mi]);
            size_t yo = (size_t)t*GT*HH + (size_t)m*HH + j;
            Y[yo] = h;
            __nv_bfloat16 hh = __float2bfloat16(h);
            Yhi[yo] = hh;
            Ylo[yo] = __float2bfloat16(h - __bfloat162float(hh));
        }
        grid_barrier(nb, sense);
    }
    #pragma unroll
    for (int mi = 0; mi < 4; mi++)
        Cfin[(size_t)(m0 + ty + mi*4)*HH + j] = c[mi];
}

__global__ void snap_k(const float* __restrict__ Yt, const float* __restrict__ C,
                       const int* __restrict__ tord, float* dh, float* dc)
{
    int b = blockIdx.x, h = threadIdx.x;
    int row = (*tord)*64 + b;
    dh[b*HH + h] = Yt[(size_t)row*HH + h];
    dc[b*HH + h] = C[(size_t)row*HH + h];
}

__global__ void attn_k(const float* __restrict__ Y3, const float* __restrict__ attnW,
                       float* __restrict__ attn)
{
    int b = blockIdx.x, tid = threadIdx.x;
    __shared__ float wae[HH];
    __shared__ float sc[GT];
    __shared__ float red[256];
    wae[tid] = attnW[HH + tid];
    __syncthreads();
    for (int idx = tid; idx < GT; idx += 256){
        int g = idx % GG, t = idx / GG;
        const float* row = Y3 + ((size_t)(t*GT + g*64 + b))*HH;
        float s = 0.f;
        #pragma unroll 4
        for (int h = 0; h < HH; h++) s += row[h]*wae[h];
        sc[idx] = s;
    }
    __syncthreads();
    float mx = -1e30f;
    for (int idx = tid; idx < GT; idx += 256) mx = fmaxf(mx, sc[idx]);
    red[tid] = mx; __syncthreads();
    for (int s = 128; s > 0; s >>= 1){ if (tid < s) red[tid] = fmaxf(red[tid], red[tid+s]); __syncthreads(); }
    mx = red[0]; __syncthreads();
    float sm = 0.f;
    for (int idx = tid; idx < GT; idx += 256){ float e = expf(sc[idx]-mx); sc[idx] = e; sm += e; }
    red[tid] = sm; __syncthreads();
    for (int s = 128; s > 0; s >>= 1){ if (tid < s) red[tid] += red[tid+s]; __syncthreads(); }
    float inv = 1.f/red[0];
    __syncthreads();
    float a0 = 0.f;
    for (int idx = 0; idx < GT; idx++){
        int g = idx % GG, t = idx / GG;
        a0 += sc[idx]*Y3[((size_t)(t*GT + g*64 + b))*HH + tid];
    }
    attn[b*HH + tid] = a0*inv;
}

__global__ void pack_cin_k(const float* dh0, const float* attn, float* cin)
{
    int b = blockIdx.x, k = threadIdx.x;
    cin[b*512 + k] = (k < HH) ? dh0[b*HH + k] : attn[b*HH + (k - HH)];
}

// Persistent decoder: 64 steps x 4 layers, one launch. 192 blocks x 128 thr.
__global__ __launch_bounds__(128, 2) void dec_persist_k(
    const float* __restrict__ x, const int* __restrict__ tord,
    const float* __restrict__ cnst, const float* __restrict__ cinAll,
    const float* __restrict__ WeT, const float* __restrict__ WihsT,
    float* __restrict__ H1, float* __restrict__ H2,
    const float* __restrict__ outW, const float* __restrict__ outB,
    const float* __restrict__ Wemb, const float* __restrict__ bemb,
    float* __restrict__ dout)
{
    __shared__ float sE[8][128];
    __shared__ float sIn[8][33];
    __shared__ float sW[32][4][32];
    __shared__ float sRed[8][16];
    __shared__ float sOut[8][4];
    const int tid = threadIdx.x;
    const int tx = tid & 31, ty = tid >> 5;
    const int jc = blockIdx.x & 7;
    const int m0 = (blockIdx.x >> 3)*8, j0 = jc*32;
    const unsigned nb = gridDim.x;
    unsigned sense = 0;
    const int tordv = *tord;
    const int j = j0 + tx;
    for (int t = 0; t < 64; t++){
        if (t == 0){
            for (int idx = tid; idx < 8*128; idx += 128){
                int rr = idx >> 7, e = idx & 127;
                int m = m0 + rr;
                const float* xr = x + (((size_t)((m & 63)*TT_ + 63))*GG + (tordv + (m >> 6)))*FF;
                float v = bemb[e] + xr[0]*Wemb[e*4] + xr[1]*Wemb[e*4+1]
                                  + xr[2]*Wemb[e*4+2] + xr[3]*Wemb[e*4+3];
                sE[rr][e] = fmaxf(v, 0.f);
            }
            __syncthreads();
        } else {
            {
                int r = tid >> 4, sub = tid & 15, o = sub & 3, seg = sub >> 2;
                const float* hrow = H2 + (size_t)(m0 + r)*HH;
                float s = 0.f;
                #pragma unroll 4
                for (int h = seg*64; h < seg*64 + 64; h++)
                    s += __ldcg(hrow + h) * outW[o*HH + h];
                sRed[r][sub] = s;
            }
            __syncthreads();
            if (tid < 32){
                int rr = tid >> 2, oo = tid & 3;
                float v = sRed[rr][oo] + sRed[rr][4+oo] + sRed[rr][8+oo] + sRed[rr][12+oo] + outB[oo];
                sOut[rr][oo] = v;
                if (jc == 0){
                    int m = m0 + rr;
                    dout[(size_t)(m & 63)*(TT_*NT*FF) + (size_t)(t-1)*(NT*FF) + (m >> 6)*FF + oo] = v;
                }
            }
            __syncthreads();
            for (int idx = tid; idx < 8*128; idx += 128){
                int rr = idx >> 7, e = idx & 127;
                float v = bemb[e] + sOut[rr][0]*Wemb[e*4] + sOut[rr][1]*Wemb[e*4+1]
                        + sOut[rr][2]*Wemb[e*4+2] + sOut[rr][3]*Wemb[e*4+3];
                sE[rr][e] = fmaxf(v, 0.f);
            }
            __syncthreads();
        }
        for (int l = 0; l < 4; l++){
            float acc[2][4] = {{0.f,0.f,0.f,0.f},{0.f,0.f,0.f,0.f}};
            const float* Wt = (l == 0) ? WeT : (WihsT + (size_t)(l-1)*KSZ);
            const int K = (l == 0) ? EE : HH;
            const float* In = (l == 2) ? H2 : H1;
            float* Ho = (l == 0 || l == 2) ? H1 : H2;
            for (int k0 = 0; k0 < K; k0 += 32){
                if (l > 0 && tid < 64){
                    int r = tid >> 3, kc = (tid & 7)*4;
                    float4 v = __ldcg(reinterpret_cast<const float4*>(In + (size_t)(m0+r)*HH + k0 + kc));
                    sIn[r][kc] = v.x; sIn[r][kc+1] = v.y; sIn[r][kc+2] = v.z; sIn[r][kc+3] = v.w;
                }
                #pragma unroll
                for (int qq = 0; qq < 32; qq++){
                    int lin = qq*128 + tid;
                    int kr = lin >> 7, col = lin & 127;
                    sW[kr][col >> 5][col & 31] =
                        Wt[(size_t)(k0+kr)*NG + (col >> 5)*HH + j0 + (col & 31)];
                }
                __syncthreads();
                #pragma unroll
                for (int kk = 0; kk < 32; kk++){
                    float w0 = sW[kk][0][tx], w1 = sW[kk][1][tx];
                    float w2 = sW[kk][2][tx], w3 = sW[kk][3][tx];
                    float a0 = (l == 0) ? sE[ty*2][k0+kk]   : sIn[ty*2][kk];
                    float a1 = (l == 0) ? sE[ty*2+1][k0+kk] : sIn[ty*2+1][kk];
                    acc[0][0]+=a0*w0; acc[0][1]+=a0*w1; acc[0][2]+=a0*w2; acc[0][3]+=a0*w3;
                    acc[1][0]+=a1*w0; acc[1][1]+=a1*w1; acc[1][2]+=a1*w2; acc[1][3]+=a1*w3;
                }
                __syncthreads();
            }
            const float* cl = cnst + (size_t)l*BB*NG;
            const float* ci = cinAll + (size_t)l*BB*HH;
            #pragma unroll
            for (int rr = 0; rr < 2; rr++){
                int m = m0 + ty*2 + rr, b = m & 63;
                const float* cp = cl + (size_t)b*NG;
                float gi = acc[rr][0] + cp[j];
                float gf = acc[rr][1] + cp[HH + j];
                float gg = acc[rr][2] + cp[2*HH + j];
                float go = acc[rr][3] + cp[3*HH + j];
                float c2 = sigmoidf(gf)*ci[b*HH + j] + sigmoidf(gi)*tanhf(gg);
                Ho[(size_t)m*HH + j] = sigmoidf(go)*tanhf(c2);
            }
            grid_barrier(nb, sense);
        }
    }
    {
        int r = tid >> 4, sub = tid & 15, o = sub & 3, seg = sub >> 2;
        const float* hrow = H2 + (size_t)(m0 + r)*HH;
        float s = 0.f;
        #pragma unroll 4
        for (int h = seg*64; h < seg*64 + 64; h++)
            s += __ldcg(hrow + h) * outW[o*HH + h];
        sRed[r][sub] = s;
    }
    __syncthreads();
    if (tid < 32 && jc == 0){
        int rr = tid >> 2, oo = tid & 3;
        float v = sRed[rr][oo] + sRed[rr][4+oo] + sRed[rr][8+oo] + sRed[rr][12+oo] + outB[oo];
        int m = m0 + rr;
        dout[(size_t)(m & 63)*(TT_*NT*FF) + 63u*(NT*FF) + (m >> 6)*FF + oo] = v;
    }
}

static float* symaddr(const void* sym)
{
    void* p = nullptr;
    cudaGetSymbolAddress(&p, sym);
    return (float*)p;
}

extern "C" void kernel_launch(void* const* d_in, const int* in_sizes, int n_in,
                              void* d_out, int out_size)
{
    (void)in_sizes; (void)n_in; (void)out_size;
    const float* x       = (const float*)d_in[0];
    const float* encLinW = (const float*)d_in[2];
    const float* encLinB = (const float*)d_in[3];
    const float* encWih0 = (const float*)d_in[4];
    const float* encWihs = (const float*)d_in[5];
    const float* encWhh  = (const float*)d_in[6];
    const float* encBih  = (const float*)d_in[7];
    const float* encBhh  = (const float*)d_in[8];
    const float* decEmbW = (const float*)d_in[9];
    const float* decEmbB = (const float*)d_in[10];
    const float* attnW   = (const float*)d_in[11];
    const float* decWih0 = (const float*)d_in[13];
    const float* decWihs = (const float*)d_in[14];
    const float* decWhh  = (const float*)d_in[15];
    const float* decBih  = (const float*)d_in[16];
    const float* decBhh  = (const float*)d_in[17];
    const float* outW    = (const float*)d_in[18];
    const float* outB    = (const float*)d_in[19];
    const int*   tord    = (const int*)d_in[20];
    float* out = (float*)d_out;

    float* pX = symaddr(g_X);
    float* pY0 = symaddr(g_Y0);
    float* pY1 = symaddr(g_Y1);
    float* pC = symaddr(g_Cst);
    __nv_bfloat16* pAhi = (__nv_bfloat16*)symaddr(g_Ahi);
    __nv_bfloat16* pAlo = (__nv_bfloat16*)symaddr(g_Alo);
    __nv_bfloat16* pWhi = (__nv_bfloat16*)symaddr(g_Whi);
    __nv_bfloat16* pWlo = (__nv_bfloat16*)symaddr(g_Wlo);
    float* pWhhT = symaddr(g_encWhhT);
    float* pBiasEnc = symaddr(g_biasEnc);
    float* pDecWihsT = symaddr(g_decWihsT);
    float* pDecWhhT = symaddr(g_decWhhT);
    float* pPack = symaddr(g_WcPack);
    float* pWeT = symaddr(g_decWeT);
    float* pBiasDec = symaddr(g_biasDec);
    float* pDech = symaddr(g_dech);
    float* pDecc = symaddr(g_decc);
    float* pAttn = symaddr(g_attn);
    float* pCin = symaddr(g_cin);
    float* pConst = symaddr(g_const);
    float* pH1 = symaddr(g_h1);
    float* pH2 = symaddr(g_h2);

    dim3 tb(32, 8);
    // weight prep: bf16 hi/lo splits of Wih (no transpose needed: [n][k] row-major)
    wsplit_k<<<(NG*EE + 255)/256, 256>>>(encWih0, pWhi, pWlo, NG*EE);
    for (int l = 1; l < 4; l++)
        wsplit_k<<<(NG*HH + 255)/256, 256>>>(encWihs + (size_t)(l-1)*NG*HH,
                                             pWhi + NG*EE + (size_t)(l-1)*NG*HH,
                                             pWlo + NG*EE + (size_t)(l-1)*NG*HH, NG*HH);
    for (int l = 0; l < 4; l++)
        transpose_k<<<dim3(8, 32), tb>>>(encWhh + (size_t)l*NG*HH, HH, NG, HH, pWhhT + (size_t)l*KSZ, NG);
    addv_k<<<16, 256>>>(encBih, encBhh, pBiasEnc, 4*NG);
    for (int l = 0; l < 3; l++)
        transpose_k<<<dim3(8, 32), tb>>>(decWihs + (size_t)l*NG*HH, HH, NG, HH, pDecWihsT + (size_t)l*KSZ, NG);
    for (int l = 1; l < 4; l++)
        transpose_k<<<dim3(8, 32), tb>>>(decWhh + (size_t)l*NG*HH, HH, NG, HH, pDecWhhT + (size_t)(l-1)*KSZ, NG);
    transpose_k<<<dim3(8, 32), tb>>>(decWhh, HH, NG, HH, pPack, NG);
    transpose_k<<<dim3(8, 32), tb>>>(decWih0, 384, NG, HH, pPack + (size_t)HH*NG, NG);
    transpose_k<<<dim3(4, 32), tb>>>(decWih0 + HH, 384, NG, EE, pWeT, NG);
    addv_k<<<16, 256>>>(decBih, decBhh, pBiasDec, 4*NG);

    // encoder embedding (bf16 hi/lo)
    emb_k<<<MTOT, 128>>>(x, encLinW, encLinB, pAhi, pAlo);

    // encoder: tensor-core input GEMM + persistent recurrence per layer
    float* Ybuf[2] = { pY0, pY1 };
    for (int l = 0; l < 4; l++){
        const __nv_bfloat16* wh = (l == 0) ? pWhi : (pWhi + NG*EE + (size_t)(l-1)*NG*HH);
        const __nv_bfloat16* wl = (l == 0) ? pWlo : (pWlo + NG*EE + (size_t)(l-1)*NG*HH);
        int Kin = (l == 0) ? EE : HH;
        gemm_tc_k<<<dim3(8, MTOT/128), 256>>>(pAhi, pAlo, wh, wl, pBiasEnc + l*NG, pX, Kin);
        float* Yc = Ybuf[l & 1];
        enc_layer_k<<<352, 128>>>(pX, pWhhT + (size_t)l*KSZ, Yc, pC, pAhi, pAlo);
        snap_k<<<64, 256>>>(Yc + (size_t)(TT_-1)*GT*HH, pC, tord,
                            pDech + (size_t)l*BB*HH, pDecc + (size_t)l*BB*HH);
    }
    float* Ytop = pY1;

    attn_k<<<BB, 256>>>(Ytop, attnW, pAttn);
    pack_cin_k<<<BB, 512>>>(pDech, pAttn, pCin);
    gemm_k<<<dim3(8, 1), 256>>>(pCin, pPack, pBiasDec, pConst, BB, NG, 512);
    for (int l = 1; l < 4; l++)
        gemm_k<<<dim3(8, 1), 256>>>(pDech + (size_t)l*BB*HH, pDecWhhT + (size_t)(l-1)*KSZ,
                                    pBiasDec + l*NG, pConst + (size_t)l*BB*NG, BB, NG, HH);

    dec_persist_k<<<192, 128>>>(x, tord, pConst, pDecc, pWeT, pDecWihsT,
                                pH1, pH2, outW, outB, decEmbW, decEmbB, out);
}

// round 8
// speedup vs baseline: 1.7983x; 1.3773x over previous
#include <cuda_runtime.h>
#include <cuda_bf16.h>
#include <cstdint>

#define BB   64
#define TT_  64
#define GG   11
#define FF   4
#define HH   256
#define EE   128
#define NT   3
#define GT   (GG*BB)     // 704
#define MTOT (TT_*GT)    // 45056
#define NG   1024
#define KSZ  (256*1024)

// encoder tc persistent tile
#define ER 64
#define EC 128
#define BP 132
#define AP 132
#define SB_WORDS (2*128*BP)            // 33792
#define SA_WORDS (2*64*AP)             // 16896
#define SMEM_ENC ((SB_WORDS + SA_WORDS)*4)  // 202752 B

__device__ float g_X[MTOT*NG];
__device__ float g_Y0[MTOT*HH];
__device__ float g_Cst[GT*HH];
__device__ __nv_bfloat16 g_Ahi[MTOT*HH];
__device__ __nv_bfloat16 g_Alo[MTOT*HH];
__device__ __nv_bfloat16 g_WihHi[(EE + 3*HH)*NG];
__device__ __nv_bfloat16 g_WihLo[(EE + 3*HH)*NG];
__device__ __nv_bfloat16 g_WhhHi[4*NG*HH];
__device__ __nv_bfloat16 g_WhhLo[4*NG*HH];
__device__ float g_biasEncP[4*NG];
__device__ float g_decWihsT[3*KSZ];
__device__ float g_decWhhT[3*KSZ];
__device__ float g_WcPack[512*NG];
__device__ float g_decWeT[EE*NG];
__device__ float g_biasDec[4*NG];
__device__ float g_dech[4*BB*HH];
__device__ float g_decc[4*BB*HH];
__device__ float g_attn[BB*HH];
__device__ float g_cin[BB*512];
__device__ float g_const[4*BB*NG];
__device__ float g_h1[NT*BB*HH];
__device__ float g_h2[NT*BB*HH];
__device__ unsigned g_bcnt = 0;
__device__ unsigned g_bsense = 0;

__device__ __forceinline__ float sigmoidf(float x){ return 1.f/(1.f + expf(-x)); }

__device__ __host__ __forceinline__ int permn(int n)
{
    int gate = n >> 8, h = n & 255;
    return (h >> 1)*8 + gate*2 + (h & 1);
}

__device__ __forceinline__ void grid_barrier(unsigned nb, unsigned& sense)
{
    __syncthreads();
    if (threadIdx.x == 0){
        unsigned want = sense ^ 1u;
        __threadfence();
        if (atomicAdd(&g_bcnt, 1u) == nb - 1u){
            atomicExch(&g_bcnt, 0u);
            __threadfence();
            atomicExch(&g_bsense, want);
        } else {
            while (atomicAdd(&g_bsense, 0u) != want) __nanosleep(64);
        }
        __threadfence();
    }
    __syncthreads();
    sense ^= 1u;
}

__global__ void transpose_k(const float* __restrict__ src, int ldS, int rows, int cols,
                            float* __restrict__ dst, int ldD)
{
    __shared__ float tile[32][33];
    int c0 = blockIdx.x*32, r0 = blockIdx.y*32;
    for (int i = threadIdx.y; i < 32; i += 8){
        int r = r0 + i, c = c0 + threadIdx.x;
        tile[i][threadIdx.x] = (r < rows && c < cols) ? src[(size_t)r*ldS + c] : 0.f;
    }
    __syncthreads();
    for (int i = threadIdx.y; i < 32; i += 8){
        int c = c0 + i, r = r0 + threadIdx.x;
        if (c < cols && r < rows) dst[(size_t)c*ldD + r] = tile[threadIdx.x][i];
    }
}

__global__ void addv_k(const float* a, const float* b, float* o, int n)
{
    int i = blockIdx.x*256 + threadIdx.x;
    if (i < n) o[i] = a[i] + b[i];
}

__global__ void addv_perm_k(const float* __restrict__ a, const float* __restrict__ b,
                            float* __restrict__ o)
{
    int n = blockIdx.x*256 + threadIdx.x;
    if (n < NG) o[permn(n)] = a[n] + b[n];
}

__global__ void wsplit_perm_k(const float* __restrict__ src, int K,
                              __nv_bfloat16* __restrict__ hi, __nv_bfloat16* __restrict__ lo)
{
    int i = blockIdx.x*256 + threadIdx.x;
    if (i < NG*K){
        int n = i / K, k = i - n*K;
        float v = src[i];
        __nv_bfloat16 h = __float2bfloat16(v);
        int d = permn(n)*K + k;
        hi[d] = h;
        lo[d] = __float2bfloat16(v - __bfloat162float(h));
    }
}

__global__ void emb_k(const float* __restrict__ x, const float* __restrict__ W,
                      const float* __restrict__ bias,
                      __nv_bfloat16* __restrict__ hi, __nv_bfloat16* __restrict__ lo)
{
    int m = blockIdx.x;
    int t = m / GT; int rem = m % GT; int g = rem >> 6; int b = rem & 63;
    const float* xr = x + (((size_t)(b*TT_ + t))*GG + g)*FF;
    int e = threadIdx.x;
    float v = bias[e] + xr[0]*W[e*4] + xr[1]*W[e*4+1] + xr[2]*W[e*4+2] + xr[3]*W[e*4+3];
    v = fmaxf(v, 0.f);
    __nv_bfloat16 h = __float2bfloat16(v);
    hi[(size_t)m*EE + e] = h;
    lo[(size_t)m*EE + e] = __float2bfloat16(v - __bfloat162float(h));
}

__device__ __forceinline__ void mma_bf16(float* c, const uint32_t* a, uint32_t b0, uint32_t b1)
{
    asm volatile("mma.sync.aligned.m16n8k16.row.col.f32.bf16.bf16.f32 "
        "{%0,%1,%2,%3}, {%4,%5,%6,%7}, {%8,%9}, {%0,%1,%2,%3};"
        : "+f"(c[0]), "+f"(c[1]), "+f"(c[2]), "+f"(c[3])
        : "r"(a[0]), "r"(a[1]), "r"(a[2]), "r"(a[3]), "r"(b0), "r"(b1));
}

// Tensor-core split-bf16 GEMM: C[M][1024] = A[M][K] @ W[1024][K]^T + bias
__global__ __launch_bounds__(256, 2) void gemm_tc_k(
    const __nv_bfloat16* __restrict__ Ahi, const __nv_bfloat16* __restrict__ Alo,
    const __nv_bfloat16* __restrict__ Whi, const __nv_bfloat16* __restrict__ Wlo,
    const float* __restrict__ bias, float* __restrict__ C, int K)
{
    __shared__ __align__(16) uint32_t sA[2][128][20];
    __shared__ __align__(16) uint32_t sB[2][128][20];
    const int tid = threadIdx.x;
    const int lane = tid & 31, wid = tid >> 5;
    const int wm = wid & 3, wn = wid >> 2;
    const int m0 = blockIdx.y*128, n0 = blockIdx.x*128;
    const int g = lane >> 2, q = lane & 3;
    float acc[2][8][4];
    #pragma unroll
    for (int i = 0; i < 2; i++)
        #pragma unroll
        for (int j = 0; j < 8; j++){ acc[i][j][0]=0.f; acc[i][j][1]=0.f; acc[i][j][2]=0.f; acc[i][j][3]=0.f; }

    for (int k0 = 0; k0 < K; k0 += 32){
        #pragma unroll
        for (int rep = 0; rep < 2; rep++){
            int chunk = tid + rep*256;
            int row = chunk >> 2, off = chunk & 3;
            size_t ga = (size_t)(m0 + row)*K + k0 + off*8;
            size_t gb = (size_t)(n0 + row)*K + k0 + off*8;
            *reinterpret_cast<uint4*>(&sA[0][row][off*4]) = *reinterpret_cast<const uint4*>(Ahi + ga);
            *reinterpret_cast<uint4*>(&sA[1][row][off*4]) = *reinterpret_cast<const uint4*>(Alo + ga);
            *reinterpret_cast<uint4*>(&sB[0][row][off*4]) = *reinterpret_cast<const uint4*>(Whi + gb);
            *reinterpret_cast<uint4*>(&sB[1][row][off*4]) = *reinterpret_cast<const uint4*>(Wlo + gb);
        }
        __syncthreads();
        #pragma unroll
        for (int ks = 0; ks < 2; ks++){
            int kp = q + ks*8;
            uint32_t a[2][2][4];
            #pragma unroll
            for (int fm = 0; fm < 2; fm++){
                int row = wm*32 + fm*16;
                #pragma unroll
                for (int s = 0; s < 2; s++){
                    a[fm][s][0] = sA[s][row+g][kp];
                    a[fm][s][1] = sA[s][row+g+8][kp];
                    a[fm][s][2] = sA[s][row+g][kp+4];
                    a[fm][s][3] = sA[s][row+g+8][kp+4];
                }
            }
            #pragma unroll
            for (int fn = 0; fn < 8; fn++){
                int nr = wn*64 + fn*8 + g;
                uint32_t bh0 = sB[0][nr][kp], bh1 = sB[0][nr][kp+4];
                uint32_t bl0 = sB[1][nr][kp], bl1 = sB[1][nr][kp+4];
                #pragma unroll
                for (int fm = 0; fm < 2; fm++){
                    mma_bf16(acc[fm][fn], a[fm][0], bh0, bh1);
                    mma_bf16(acc[fm][fn], a[fm][0], bl0, bl1);
                    mma_bf16(acc[fm][fn], a[fm][1], bh0, bh1);
                }
            }
        }
        __syncthreads();
    }
    #pragma unroll
    for (int fm = 0; fm < 2; fm++){
        int r = m0 + wm*32 + fm*16 + g;
        #pragma unroll
        for (int fn = 0; fn < 8; fn++){
            int cn = n0 + wn*64 + fn*8 + q*2;
            float b0 = bias[cn], b1 = bias[cn+1];
            float2 v0 = make_float2(acc[fm][fn][0] + b0, acc[fm][fn][1] + b1);
            float2 v1 = make_float2(acc[fm][fn][2] + b0, acc[fm][fn][3] + b1);
            *reinterpret_cast<float2*>(C + (size_t)r*NG + cn) = v0;
            *reinterpret_cast<float2*>(C + (size_t)(r+8)*NG + cn) = v1;
        }
    }
}

// fp32 GEMM (decoder constants)
__global__ void gemm_k(const float* __restrict__ A, const float* __restrict__ B,
                       const float* __restrict__ bias, float* __restrict__ C,
                       int M, int N, int K)
{
    __shared__ float As[8][128];
    __shared__ float Bs[8][128];
    int tid = threadIdx.x;
    int m0 = blockIdx.y*128, n0 = blockIdx.x*128;
    int tx = tid & 15, ty = tid >> 4;
    float acc[8][8];
    #pragma unroll
    for (int i = 0; i < 8; i++)
        #pragma unroll
        for (int j = 0; j < 8; j++) acc[i][j] = 0.f;
    int arow = tid >> 1, acol = (tid & 1)*4;
    int brow = tid >> 5, bcol = (tid & 31)*4;
    for (int k0 = 0; k0 < K; k0 += 8){
        float4 av = make_float4(0.f,0.f,0.f,0.f);
        int gm = m0 + arow;
        if (gm < M) av = *reinterpret_cast<const float4*>(A + (size_t)gm*K + k0 + acol);
        As[acol+0][arow] = av.x; As[acol+1][arow] = av.y;
        As[acol+2][arow] = av.z; As[acol+3][arow] = av.w;
        *reinterpret_cast<float4*>(&Bs[brow][bcol]) =
            *reinterpret_cast<const float4*>(B + (size_t)(k0+brow)*N + n0 + bcol);
        __syncthreads();
        #pragma unroll
        for (int kk = 0; kk < 8; kk++){
            float a[8], b[8];
            *reinterpret_cast<float4*>(a)   = *reinterpret_cast<float4*>(&As[kk][ty*4]);
            *reinterpret_cast<float4*>(a+4) = *reinterpret_cast<float4*>(&As[kk][64+ty*4]);
            *reinterpret_cast<float4*>(b)   = *reinterpret_cast<float4*>(&Bs[kk][tx*4]);
            *reinterpret_cast<float4*>(b+4) = *reinterpret_cast<float4*>(&Bs[kk][64+tx*4]);
            #pragma unroll
            for (int i = 0; i < 8; i++)
                #pragma unroll
                for (int j = 0; j < 8; j++) acc[i][j] += a[i]*b[j];
        }
        __syncthreads();
    }
    #pragma unroll
    for (int i = 0; i < 8; i++){
        int gm = m0 + ((i < 4) ? (ty*4 + i) : (64 + ty*4 + (i-4)));
        if (gm >= M) continue;
        #pragma unroll
        for (int j = 0; j < 8; j++){
            int gn = n0 + ((j < 4) ? (tx*4 + j) : (64 + tx*4 + (j-4)));
            C[(size_t)gm*N + gn] = acc[i][j] + bias[gn];
        }
    }
}

// ---------------------------------------------------------------------------
// Persistent tensor-core encoder layer: 64 steps, one launch, 88 blocks.
// Block = 64 rows x 128 permuted gate-cols (= 32 h-cols, all 4 gates).
// Whh tile (bf16 hi/lo) resident in smem for all steps; split-3-term mma.
// ---------------------------------------------------------------------------
extern __shared__ uint32_t sdyn[];

__global__ void __launch_bounds__(256, 1) enc_tc_k(
    const float* __restrict__ X,
    const __nv_bfloat16* __restrict__ WHi, const __nv_bfloat16* __restrict__ WLo,
    float* __restrict__ Y, float* __restrict__ Cfin,
    __nv_bfloat16* __restrict__ Hhi, __nv_bfloat16* __restrict__ Hlo)
{
    uint32_t* sB = sdyn;                 // [2][128][BP]
    uint32_t* sA = sdyn + SB_WORDS;      // [2][64][AP]
    float* sG = reinterpret_cast<float*>(sA);  // [64][AP] (aliased)
    const int tid = threadIdx.x;
    const int lane = tid & 31, wid = tid >> 5;
    const int wm = wid & 1, wn = wid >> 1;     // 2 m-warps x 4 n-warps
    const int g = lane >> 2, q = lane & 3;
    const int rt = blockIdx.x % 11, ct = blockIdx.x / 11;
    const int m0 = rt*ER, n0 = ct*EC;
    const unsigned nb = gridDim.x;
    unsigned sense = 0;

    // load Whh tile once (hi/lo)
    for (int i = tid; i < 2*128*32; i += 256){
        int s = i >> 12;
        int rem = i & 4095;
        int row = rem >> 5, w4 = rem & 31;
        const uint4* src = reinterpret_cast<const uint4*>(
            (s ? WLo : WHi) + (size_t)(n0 + row)*HH) + w4;
        *reinterpret_cast<uint4*>(&sB[s*128*BP + row*BP + w4*4]) = *src;
    }
    __syncthreads();

    const int erow = tid >> 2;          // 0..63
    const int hb = (tid & 3)*8;         // h block of 8 (local h offset)
    float c[8];
    #pragma unroll
    for (int e = 0; e < 8; e++) c[e] = 0.f;

    for (int t = 0; t < 64; t++){
        if (t > 0){
            // stage h(t-1) hi/lo
            for (int i = tid; i < 2*64*32; i += 256){
                int s = i >> 11;
                int rem = i & 2047;
                int row = rem >> 5, w4 = rem & 31;
                const uint4* src = reinterpret_cast<const uint4*>(
                    (s ? Hlo : Hhi) + ((size_t)(t-1)*GT + m0 + row)*HH) + w4;
                uint4 v = __ldcg(src);
                *reinterpret_cast<uint4*>(&sA[s*64*AP + row*AP + w4*4]) = v;
            }
            __syncthreads();
            float acc[2][4][4];
            #pragma unroll
            for (int i = 0; i < 2; i++)
                #pragma unroll
                for (int j = 0; j < 4; j++){ acc[i][j][0]=0.f; acc[i][j][1]=0.f; acc[i][j][2]=0.f; acc[i][j][3]=0.f; }
            #pragma unroll
            for (int ks = 0; ks < 16; ks++){
                const int kp = ks*8 + q;
                uint32_t a[2][2][4];
                #pragma unroll
                for (int fm = 0; fm < 2; fm++){
                    int row = wm*32 + fm*16;
                    #pragma unroll
                    for (int s = 0; s < 2; s++){
                        const uint32_t* base = sA + s*64*AP;
                        a[fm][s][0] = base[(row+g)*AP + kp];
                        a[fm][s][1] = base[(row+g+8)*AP + kp];
                        a[fm][s][2] = base[(row+g)*AP + kp+4];
                        a[fm][s][3] = base[(row+g+8)*AP + kp+4];
                    }
                }
                #pragma unroll
                for (int fn = 0; fn < 4; fn++){
                    int nr = wn*32 + fn*8 + g;
                    uint32_t bh0 = sB[nr*BP + kp], bh1 = sB[nr*BP + kp+4];
                    uint32_t bl0 = sB[128*BP + nr*BP + kp], bl1 = sB[128*BP + nr*BP + kp+4];
                    #pragma unroll
                    for (int fm = 0; fm < 2; fm++){
                        mma_bf16(acc[fm][fn], a[fm][0], bh0, bh1);
                        mma_bf16(acc[fm][fn], a[fm][0], bl0, bl1);
                        mma_bf16(acc[fm][fn], a[fm][1], bh0, bh1);
                    }
                }
            }
            __syncthreads();   // done reading sA -> reuse as sG
            #pragma unroll
            for (int fm = 0; fm < 2; fm++){
                int r1 = wm*32 + fm*16 + g;
                #pragma unroll
                for (int fn = 0; fn < 4; fn++){
                    int c0 = wn*32 + fn*8 + q*2;
                    *reinterpret_cast<float2*>(&sG[r1*AP + c0]) =
                        make_float2(acc[fm][fn][0], acc[fm][fn][1]);
                    *reinterpret_cast<float2*>(&sG[(r1+8)*AP + c0]) =
                        make_float2(acc[fm][fn][2], acc[fm][fn][3]);
                }
            }
            __syncthreads();
        }
        // LSTM epilogue: 8 h per thread (4 h-pairs). Local h = hb + 2*ep + {0,1}.
        const float* xp = X + ((size_t)t*GT + m0 + erow)*NG + n0;
        const size_t yb = ((size_t)t*GT + m0 + erow)*HH + ct*32 + hb;   // FIX: + hb
        #pragma unroll
        for (int ep = 0; ep < 4; ep++){
            int h2 = (hb >> 1) + ep;
            int cb = h2*8;
            float4 x0 = *reinterpret_cast<const float4*>(xp + cb);
            float4 x1 = *reinterpret_cast<const float4*>(xp + cb + 4);
            float gi0 = x0.x, gi1 = x0.y, gf0 = x0.z, gf1 = x0.w;
            float gg0 = x1.x, gg1 = x1.y, go0 = x1.z, go1 = x1.w;
            if (t > 0){
                float4 s0 = *reinterpret_cast<const float4*>(&sG[erow*AP + cb]);
                float4 s1 = *reinterpret_cast<const float4*>(&sG[erow*AP + cb + 4]);
                gi0 += s0.x; gi1 += s0.y; gf0 += s0.z; gf1 += s0.w;
                gg0 += s1.x; gg1 += s1.y; go0 += s1.z; go1 += s1.w;
            }
            float c0 = sigmoidf(gf0)*c[ep*2]   + sigmoidf(gi0)*tanhf(gg0);
            float c1 = sigmoidf(gf1)*c[ep*2+1] + sigmoidf(gi1)*tanhf(gg1);
            c[ep*2] = c0; c[ep*2+1] = c1;
            float h0 = sigmoidf(go0)*tanhf(c0);
            float h1 = sigmoidf(go1)*tanhf(c1);
            *reinterpret_cast<float2*>(Y + yb + 2*ep) = make_float2(h0, h1);
            __nv_bfloat16 b0 = __float2bfloat16(h0), b1 = __float2bfloat16(h1);
            __nv_bfloat162 hhv; hhv.x = b0; hhv.y = b1;
            __nv_bfloat162 llv;
            llv.x = __float2bfloat16(h0 - __bfloat162float(b0));
            llv.y = __float2bfloat16(h1 - __bfloat162float(b1));
            *reinterpret_cast<__nv_bfloat162*>(Hhi + yb + 2*ep) = hhv;
            *reinterpret_cast<__nv_bfloat162*>(Hlo + yb + 2*ep) = llv;
        }
        grid_barrier(nb, sense);
    }
    const size_t cbse = (size_t)(m0 + erow)*HH + ct*32 + hb;            // FIX: + hb
    #pragma unroll
    for (int e = 0; e < 8; e++) Cfin[cbse + 2*(e>>1) + (e&1)] = c[e];
}

__global__ void snap_k(const float* __restrict__ Yt, const float* __restrict__ C,
                       const int* __restrict__ tord, float* dh, float* dc)
{
    int b = blockIdx.x, h = threadIdx.x;
    int row = (*tord)*64 + b;
    dh[b*HH + h] = Yt[(size_t)row*HH + h];
    dc[b*HH + h] = C[(size_t)row*HH + h];
}

__global__ void attn_k(const float* __restrict__ Y3, const float* __restrict__ attnW,
                       float* __restrict__ attn)
{
    int b = blockIdx.x, tid = threadIdx.x;
    __shared__ float wae[HH];
    __shared__ float sc[GT];
    __shared__ float red[256];
    wae[tid] = attnW[HH + tid];
    __syncthreads();
    for (int idx = tid; idx < GT; idx += 256){
        int g = idx % GG, t = idx / GG;
        const float* row = Y3 + ((size_t)(t*GT + g*64 + b))*HH;
        float s = 0.f;
        #pragma unroll 4
        for (int h = 0; h < HH; h++) s += row[h]*wae[h];
        sc[idx] = s;
    }
    __syncthreads();
    float mx = -1e30f;
    for (int idx = tid; idx < GT; idx += 256) mx = fmaxf(mx, sc[idx]);
    red[tid] = mx; __syncthreads();
    for (int s = 128; s > 0; s >>= 1){ if (tid < s) red[tid] = fmaxf(red[tid], red[tid+s]); __syncthreads(); }
    mx = red[0]; __syncthreads();
    float sm = 0.f;
    for (int idx = tid; idx < GT; idx += 256){ float e = expf(sc[idx]-mx); sc[idx] = e; sm += e; }
    red[tid] = sm; __syncthreads();
    for (int s = 128; s > 0; s >>= 1){ if (tid < s) red[tid] += red[tid+s]; __syncthreads(); }
    float inv = 1.f/red[0];
    __syncthreads();
    float a0 = 0.f;
    for (int idx = 0; idx < GT; idx++){
        int g = idx % GG, t = idx / GG;
        a0 += sc[idx]*Y3[((size_t)(t*GT + g*64 + b))*HH + tid];
    }
    attn[b*HH + tid] = a0*inv;
}

__global__ void pack_cin_k(const float* dh0, const float* attn, float* cin)
{
    int b = blockIdx.x, k = threadIdx.x;
    cin[b*512 + k] = (k < HH) ? dh0[b*HH + k] : attn[b*HH + (k - HH)];
}

// Persistent decoder: 64 steps x 4 layers, one launch. 192 blocks x 128 thr.
__global__ __launch_bounds__(128, 2) void dec_persist_k(
    const float* __restrict__ x, const int* __restrict__ tord,
    const float* __restrict__ cnst, const float* __restrict__ cinAll,
    const float* __restrict__ WeT, const float* __restrict__ WihsT,
    float* __restrict__ H1, float* __restrict__ H2,
    const float* __restrict__ outW, const float* __restrict__ outB,
    const float* __restrict__ Wemb, const float* __restrict__ bemb,
    float* __restrict__ dout)
{
    __shared__ float sE[8][128];
    __shared__ float sIn[8][33];
    __shared__ float sW[32][4][32];
    __shared__ float sRed[8][16];
    __shared__ float sOut[8][4];
    const int tid = threadIdx.x;
    const int tx = tid & 31, ty = tid >> 5;
    const int jc = blockIdx.x & 7;
    const int m0 = (blockIdx.x >> 3)*8, j0 = jc*32;
    const unsigned nb = gridDim.x;
    unsigned sense = 0;
    const int tordv = *tord;
    const int j = j0 + tx;
    for (int t = 0; t < 64; t++){
        if (t == 0){
            for (int idx = tid; idx < 8*128; idx += 128){
                int rr = idx >> 7, e = idx & 127;
                int m = m0 + rr;
                const float* xr = x + (((size_t)((m & 63)*TT_ + 63))*GG + (tordv + (m >> 6)))*FF;
                float v = bemb[e] + xr[0]*Wemb[e*4] + xr[1]*Wemb[e*4+1]
                                  + xr[2]*Wemb[e*4+2] + xr[3]*Wemb[e*4+3];
                sE[rr][e] = fmaxf(v, 0.f);
            }
            __syncthreads();
        } else {
            {
                int r = tid >> 4, sub = tid & 15, o = sub & 3, seg = sub >> 2;
                const float* hrow = H2 + (size_t)(m0 + r)*HH;
                float s = 0.f;
                #pragma unroll 4
                for (int h = seg*64; h < seg*64 + 64; h++)
                    s += __ldcg(hrow + h) * outW[o*HH + h];
                sRed[r][sub] = s;
            }
            __syncthreads();
            if (tid < 32){
                int rr = tid >> 2, oo = tid & 3;
                float v = sRed[rr][oo] + sRed[rr][4+oo] + sRed[rr][8+oo] + sRed[rr][12+oo] + outB[oo];
                sOut[rr][oo] = v;
                if (jc == 0){
                    int m = m0 + rr;
                    dout[(size_t)(m & 63)*(TT_*NT*FF) + (size_t)(t-1)*(NT*FF) + (m >> 6)*FF + oo] = v;
                }
            }
            __syncthreads();
            for (int idx = tid; idx < 8*128; idx += 128){
                int rr = idx >> 7, e = idx & 127;
                float v = bemb[e] + sOut[rr][0]*Wemb[e*4] + sOut[rr][1]*Wemb[e*4+1]
                        + sOut[rr][2]*Wemb[e*4+2] + sOut[rr][3]*Wemb[e*4+3];
                sE[rr][e] = fmaxf(v, 0.f);
            }
            __syncthreads();
        }
        for (int l = 0; l < 4; l++){
            float acc[2][4] = {{0.f,0.f,0.f,0.f},{0.f,0.f,0.f,0.f}};
            const float* Wt = (l == 0) ? WeT : (WihsT + (size_t)(l-1)*KSZ);
            const int K = (l == 0) ? EE : HH;
            const float* In = (l == 2) ? H2 : H1;
            float* Ho = (l == 0 || l == 2) ? H1 : H2;
            for (int k0 = 0; k0 < K; k0 += 32){
                if (l > 0 && tid < 64){
                    int r = tid >> 3, kc = (tid & 7)*4;
                    float4 v = __ldcg(reinterpret_cast<const float4*>(In + (size_t)(m0+r)*HH + k0 + kc));
                    sIn[r][kc] = v.x; sIn[r][kc+1] = v.y; sIn[r][kc+2] = v.z; sIn[r][kc+3] = v.w;
                }
                #pragma unroll
                for (int qq = 0; qq < 32; qq++){
                    int lin = qq*128 + tid;
                    int kr = lin >> 7, col = lin & 127;
                    sW[kr][col >> 5][col & 31] =
                        Wt[(size_t)(k0+kr)*NG + (col >> 5)*HH + j0 + (col & 31)];
                }
                __syncthreads();
                #pragma unroll
                for (int kk = 0; kk < 32; kk++){
                    float w0 = sW[kk][0][tx], w1 = sW[kk][1][tx];
                    float w2 = sW[kk][2][tx], w3 = sW[kk][3][tx];
                    float a0 = (l == 0) ? sE[ty*2][k0+kk]   : sIn[ty*2][kk];
                    float a1 = (l == 0) ? sE[ty*2+1][k0+kk] : sIn[ty*2+1][kk];
                    acc[0][0]+=a0*w0; acc[0][1]+=a0*w1; acc[0][2]+=a0*w2; acc[0][3]+=a0*w3;
                    acc[1][0]+=a1*w0; acc[1][1]+=a1*w1; acc[1][2]+=a1*w2; acc[1][3]+=a1*w3;
                }
                __syncthreads();
            }
            const float* cl = cnst + (size_t)l*BB*NG;
            const float* ci = cinAll + (size_t)l*BB*HH;
            #pragma unroll
            for (int rr = 0; rr < 2; rr++){
                int m = m0 + ty*2 + rr, b = m & 63;
                const float* cp = cl + (size_t)b*NG;
                float gi = acc[rr][0] + cp[j];
                float gf = acc[rr][1] + cp[HH + j];
                float gg = acc[rr][2] + cp[2*HH + j];
                float go = acc[rr][3] + cp[3*HH + j];
                float c2 = sigmoidf(gf)*ci[b*HH + j] + sigmoidf(gi)*tanhf(gg);
                Ho[(size_t)m*HH + j] = sigmoidf(go)*tanhf(c2);
            }
            grid_barrier(nb, sense);
        }
    }
    {
        int r = tid >> 4, sub = tid & 15, o = sub & 3, seg = sub >> 2;
        const float* hrow = H2 + (size_t)(m0 + r)*HH;
        float s = 0.f;
        #pragma unroll 4
        for (int h = seg*64; h < seg*64 + 64; h++)
            s += __ldcg(hrow + h) * outW[o*HH + h];
        sRed[r][sub] = s;
    }
    __syncthreads();
    if (tid < 32 && jc == 0){
        int rr = tid >> 2, oo = tid & 3;
        float v = sRed[rr][oo] + sRed[rr][4+oo] + sRed[rr][8+oo] + sRed[rr][12+oo] + outB[oo];
        int m = m0 + rr;
        dout[(size_t)(m & 63)*(TT_*NT*FF) + 63u*(NT*FF) + (m >> 6)*FF + oo] = v;
    }
}

static float* symaddr(const void* sym)
{
    void* p = nullptr;
    cudaGetSymbolAddress(&p, sym);
    return (float*)p;
}

extern "C" void kernel_launch(void* const* d_in, const int* in_sizes, int n_in,
                              void* d_out, int out_size)
{
    (void)in_sizes; (void)n_in; (void)out_size;
    const float* x       = (const float*)d_in[0];
    const float* encLinW = (const float*)d_in[2];
    const float* encLinB = (const float*)d_in[3];
    const float* encWih0 = (const float*)d_in[4];
    const float* encWihs = (const float*)d_in[5];
    const float* encWhh  = (const float*)d_in[6];
    const float* encBih  = (const float*)d_in[7];
    const float* encBhh  = (const float*)d_in[8];
    const float* decEmbW = (const float*)d_in[9];
    const float* decEmbB = (const float*)d_in[10];
    const float* attnW   = (const float*)d_in[11];
    const float* decWih0 = (const float*)d_in[13];
    const float* decWihs = (const float*)d_in[14];
    const float* decWhh  = (const float*)d_in[15];
    const float* decBih  = (const float*)d_in[16];
    const float* decBhh  = (const float*)d_in[17];
    const float* outW    = (const float*)d_in[18];
    const float* outB    = (const float*)d_in[19];
    const int*   tord    = (const int*)d_in[20];
    float* out = (float*)d_out;

    float* pX = symaddr(g_X);
    float* pY = symaddr(g_Y0);
    float* pC = symaddr(g_Cst);
    __nv_bfloat16* pAhi = (__nv_bfloat16*)symaddr(g_Ahi);
    __nv_bfloat16* pAlo = (__nv_bfloat16*)symaddr(g_Alo);
    __nv_bfloat16* pWihHi = (__nv_bfloat16*)symaddr(g_WihHi);
    __nv_bfloat16* pWihLo = (__nv_bfloat16*)symaddr(g_WihLo);
    __nv_bfloat16* pWhhHi = (__nv_bfloat16*)symaddr(g_WhhHi);
    __nv_bfloat16* pWhhLo = (__nv_bfloat16*)symaddr(g_WhhLo);
    float* pBiasEncP = symaddr(g_biasEncP);
    float* pDecWihsT = symaddr(g_decWihsT);
    float* pDecWhhT = symaddr(g_decWhhT);
    float* pPack = symaddr(g_WcPack);
    float* pWeT = symaddr(g_decWeT);
    float* pBiasDec = symaddr(g_biasDec);
    float* pDech = symaddr(g_dech);
    float* pDecc = symaddr(g_decc);
    float* pAttn = symaddr(g_attn);
    float* pCin = symaddr(g_cin);
    float* pConst = symaddr(g_const);
    float* pH1 = symaddr(g_h1);
    float* pH2 = symaddr(g_h2);

    cudaFuncSetAttribute(enc_tc_k, cudaFuncAttributeMaxDynamicSharedMemorySize, SMEM_ENC);

    dim3 tb(32, 8);
    wsplit_perm_k<<<(NG*EE + 255)/256, 256>>>(encWih0, EE, pWihHi, pWihLo);
    for (int l = 1; l < 4; l++)
        wsplit_perm_k<<<(NG*HH + 255)/256, 256>>>(encWihs + (size_t)(l-1)*NG*HH, HH,
                                                  pWihHi + NG*EE + (size_t)(l-1)*NG*HH,
                                                  pWihLo + NG*EE + (size_t)(l-1)*NG*HH);
    for (int l = 0; l < 4; l++)
        wsplit_perm_k<<<(NG*HH + 255)/256, 256>>>(encWhh + (size_t)l*NG*HH, HH,
                                                  pWhhHi + (size_t)l*NG*HH,
                                                  pWhhLo + (size_t)l*NG*HH);
    for (int l = 0; l < 4; l++)
        addv_perm_k<<<4, 256>>>(encBih + l*NG, encBhh + l*NG, pBiasEncP + l*NG);
    for (int l = 0; l < 3; l++)
        transpose_k<<<dim3(8, 32), tb>>>(decWihs + (size_t)l*NG*HH, HH, NG, HH, pDecWihsT + (size_t)l*KSZ, NG);
    for (int l = 1; l < 4; l++)
        transpose_k<<<dim3(8, 32), tb>>>(decWhh + (size_t)l*NG*HH, HH, NG, HH, pDecWhhT + (size_t)(l-1)*KSZ, NG);
    transpose_k<<<dim3(8, 32), tb>>>(decWhh, HH, NG, HH, pPack, NG);
    transpose_k<<<dim3(8, 32), tb>>>(decWih0, 384, NG, HH, pPack + (size_t)HH*NG, NG);
    transpose_k<<<dim3(4, 32), tb>>>(decWih0 + HH, 384, NG, EE, pWeT, NG);
    addv_k<<<16, 256>>>(decBih, decBhh, pBiasDec, 4*NG);

    emb_k<<<MTOT, 128>>>(x, encLinW, encLinB, pAhi, pAlo);

    for (int l = 0; l < 4; l++){
        const __nv_bfloat16* wh = (l == 0) ? pWihHi : (pWihHi + NG*EE + (size_t)(l-1)*NG*HH);
        const __nv_bfloat16* wl = (l == 0) ? pWihLo : (pWihLo + NG*EE + (size_t)(l-1)*NG*HH);
        int Kin = (l == 0) ? EE : HH;
        gemm_tc_k<<<dim3(8, MTOT/128), 256>>>(pAhi, pAlo, wh, wl, pBiasEncP + l*NG, pX, Kin);
        enc_tc_k<<<88, 256, SMEM_ENC>>>(pX, pWhhHi + (size_t)l*NG*HH, pWhhLo + (size_t)l*NG*HH,
                                        pY, pC, pAhi, pAlo);
        snap_k<<<64, 256>>>(pY + (size_t)(TT_-1)*GT*HH, pC, tord,
                            pDech + (size_t)l*BB*HH, pDecc + (size_t)l*BB*HH);
    }

    attn_k<<<BB, 256>>>(pY, attnW, pAttn);
    pack_cin_k<<<BB, 512>>>(pDech, pAttn, pCin);
    gemm_k<<<dim3(8, 1), 256>>>(pCin, pPack, pBiasDec, pConst, BB, NG, 512);
    for (int l = 1; l < 4; l++)
        gemm_k<<<dim3(8, 1), 256>>>(pDech + (size_t)l*BB*HH, pDecWhhT + (size_t)(l-1)*KSZ,
                                    pBiasDec + l*NG, pConst + (size_t)l*BB*NG, BB, NG, HH);

    dec_persist_k<<<192, 128>>>(x, tord, pConst, pDecc, pWeT, pDecWihsT,
                                pH1, pH2, outW, outB, decEmbW, decEmbB, out);
}

// round 9
// speedup vs baseline: 1.8340x; 1.0198x over previous
#include <cuda_runtime.h>
#include <cuda_bf16.h>
#include <cstdint>

#define BB   64
#define TT_  64
#define GG   11
#define FF   4
#define HH   256
#define EE   128
#define NT   3
#define GT   (GG*BB)     // 704
#define MTOT (TT_*GT)    // 45056
#define NG   1024
#define KSZ  (256*1024)

// encoder tc persistent tile
#define ER 64
#define EC 128
#define BP 132
#define AP 132
#define SB_WORDS (2*128*BP)
#define SA_WORDS (2*64*AP)
#define SMEM_ENC ((SB_WORDS + SA_WORDS)*4)  // 202752 B

__device__ float g_X[MTOT*NG];
__device__ float g_Y0[MTOT*HH];
__device__ float g_Cst[GT*HH];
__device__ __nv_bfloat16 g_Ahi[MTOT*HH];
__device__ __nv_bfloat16 g_Alo[MTOT*HH];
__device__ __nv_bfloat16 g_WihHi[(EE + 3*HH)*NG];
__device__ __nv_bfloat16 g_WihLo[(EE + 3*HH)*NG];
__device__ __nv_bfloat16 g_WhhHi[4*NG*HH];
__device__ __nv_bfloat16 g_WhhLo[4*NG*HH];
__device__ float g_biasEncP[4*NG];
__device__ float g_decWihsT[3*KSZ];
__device__ float g_decWhhT[3*KSZ];
__device__ float g_WcPack[512*NG];
__device__ float g_decWeT[EE*NG];
__device__ float g_biasDec[4*NG];
__device__ float g_dech[4*BB*HH];
__device__ float g_decc[4*BB*HH];
__device__ float g_attn[BB*HH];
__device__ float g_cin[BB*512];
__device__ float g_const[4*BB*NG];
__device__ float g_h1[NT*BB*HH];
__device__ float g_h2[NT*BB*HH];
__device__ unsigned g_bcnt = 0;
__device__ unsigned g_flag = 0;

__device__ __forceinline__ float sigmoidf(float x){ return 1.f/(1.f + expf(-x)); }

__device__ __host__ __forceinline__ int permn(int n)
{
    int gate = n >> 8, h = n & 255;
    return (h >> 1)*8 + gate*2 + (h & 1);
}

__global__ void reset_barrier_k(){ g_bcnt = 0; g_flag = 0; }

// round-based grid barrier: atomic arrive, release store, acquire-load polling
__device__ __forceinline__ void grid_barrier(unsigned nb, unsigned& round)
{
    __syncthreads();
    if (threadIdx.x == 0){
        unsigned target = ++round;
        __threadfence();
        unsigned old = atomicAdd(&g_bcnt, 1u);
        if (old == target*nb - 1u){
            asm volatile("st.release.gpu.global.u32 [%0], %1;"
                         :: "l"(&g_flag), "r"(target) : "memory");
            __threadfence();
        } else {
            unsigned v;
            while (true){
                asm volatile("ld.acquire.gpu.global.u32 %0, [%1];"
                             : "=r"(v) : "l"(&g_flag) : "memory");
                if (v >= target) break;
                __nanosleep(32);
            }
        }
    }
    __syncthreads();
}

__global__ void transpose_k(const float* __restrict__ src, int ldS, int rows, int cols,
                            float* __restrict__ dst, int ldD)
{
    __shared__ float tile[32][33];
    int c0 = blockIdx.x*32, r0 = blockIdx.y*32;
    for (int i = threadIdx.y; i < 32; i += 8){
        int r = r0 + i, c = c0 + threadIdx.x;
        tile[i][threadIdx.x] = (r < rows && c < cols) ? src[(size_t)r*ldS + c] : 0.f;
    }
    __syncthreads();
    for (int i = threadIdx.y; i < 32; i += 8){
        int c = c0 + i, r = r0 + threadIdx.x;
        if (c < cols && r < rows) dst[(size_t)c*ldD + r] = tile[threadIdx.x][i];
    }
}

__global__ void addv_k(const float* a, const float* b, float* o, int n)
{
    int i = blockIdx.x*256 + threadIdx.x;
    if (i < n) o[i] = a[i] + b[i];
}

__global__ void addv_perm_k(const float* __restrict__ a, const float* __restrict__ b,
                            float* __restrict__ o)
{
    int n = blockIdx.x*256 + threadIdx.x;
    if (n < NG) o[permn(n)] = a[n] + b[n];
}

__global__ void wsplit_perm_k(const float* __restrict__ src, int K,
                              __nv_bfloat16* __restrict__ hi, __nv_bfloat16* __restrict__ lo)
{
    int i = blockIdx.x*256 + threadIdx.x;
    if (i < NG*K){
        int n = i / K, k = i - n*K;
        float v = src[i];
        __nv_bfloat16 h = __float2bfloat16(v);
        int d = permn(n)*K + k;
        hi[d] = h;
        lo[d] = __float2bfloat16(v - __bfloat162float(h));
    }
}

__global__ void emb_k(const float* __restrict__ x, const float* __restrict__ W,
                      const float* __restrict__ bias,
                      __nv_bfloat16* __restrict__ hi, __nv_bfloat16* __restrict__ lo)
{
    int m = blockIdx.x;
    int t = m / GT; int rem = m % GT; int g = rem >> 6; int b = rem & 63;
    const float* xr = x + (((size_t)(b*TT_ + t))*GG + g)*FF;
    int e = threadIdx.x;
    float v = bias[e] + xr[0]*W[e*4] + xr[1]*W[e*4+1] + xr[2]*W[e*4+2] + xr[3]*W[e*4+3];
    v = fmaxf(v, 0.f);
    __nv_bfloat16 h = __float2bfloat16(v);
    hi[(size_t)m*EE + e] = h;
    lo[(size_t)m*EE + e] = __float2bfloat16(v - __bfloat162float(h));
}

__device__ __forceinline__ void mma_bf16(float* c, const uint32_t* a, uint32_t b0, uint32_t b1)
{
    asm volatile("mma.sync.aligned.m16n8k16.row.col.f32.bf16.bf16.f32 "
        "{%0,%1,%2,%3}, {%4,%5,%6,%7}, {%8,%9}, {%0,%1,%2,%3};"
        : "+f"(c[0]), "+f"(c[1]), "+f"(c[2]), "+f"(c[3])
        : "r"(a[0]), "r"(a[1]), "r"(a[2]), "r"(a[3]), "r"(b0), "r"(b1));
}

// Tensor-core split-bf16 GEMM: C[M][1024] = A[M][K] @ W[1024][K]^T + bias
__global__ __launch_bounds__(256, 2) void gemm_tc_k(
    const __nv_bfloat16* __restrict__ Ahi, const __nv_bfloat16* __restrict__ Alo,
    const __nv_bfloat16* __restrict__ Whi, const __nv_bfloat16* __restrict__ Wlo,
    const float* __restrict__ bias, float* __restrict__ C, int K)
{
    __shared__ __align__(16) uint32_t sA[2][128][20];
    __shared__ __align__(16) uint32_t sB[2][128][20];
    const int tid = threadIdx.x;
    const int lane = tid & 31, wid = tid >> 5;
    const int wm = wid & 3, wn = wid >> 2;
    const int m0 = blockIdx.y*128, n0 = blockIdx.x*128;
    const int g = lane >> 2, q = lane & 3;
    float acc[2][8][4];
    #pragma unroll
    for (int i = 0; i < 2; i++)
        #pragma unroll
        for (int j = 0; j < 8; j++){ acc[i][j][0]=0.f; acc[i][j][1]=0.f; acc[i][j][2]=0.f; acc[i][j][3]=0.f; }

    for (int k0 = 0; k0 < K; k0 += 32){
        #pragma unroll
        for (int rep = 0; rep < 2; rep++){
            int chunk = tid + rep*256;
            int row = chunk >> 2, off = chunk & 3;
            size_t ga = (size_t)(m0 + row)*K + k0 + off*8;
            size_t gb = (size_t)(n0 + row)*K + k0 + off*8;
            *reinterpret_cast<uint4*>(&sA[0][row][off*4]) = *reinterpret_cast<const uint4*>(Ahi + ga);
            *reinterpret_cast<uint4*>(&sA[1][row][off*4]) = *reinterpret_cast<const uint4*>(Alo + ga);
            *reinterpret_cast<uint4*>(&sB[0][row][off*4]) = *reinterpret_cast<const uint4*>(Whi + gb);
            *reinterpret_cast<uint4*>(&sB[1][row][off*4]) = *reinterpret_cast<const uint4*>(Wlo + gb);
        }
        __syncthreads();
        #pragma unroll
        for (int ks = 0; ks < 2; ks++){
            int kp = q + ks*8;
            uint32_t a[2][2][4];
            #pragma unroll
            for (int fm = 0; fm < 2; fm++){
                int row = wm*32 + fm*16;
                #pragma unroll
                for (int s = 0; s < 2; s++){
                    a[fm][s][0] = sA[s][row+g][kp];
                    a[fm][s][1] = sA[s][row+g+8][kp];
                    a[fm][s][2] = sA[s][row+g][kp+4];
                    a[fm][s][3] = sA[s][row+g+8][kp+4];
                }
            }
            #pragma unroll
            for (int fn = 0; fn < 8; fn++){
                int nr = wn*64 + fn*8 + g;
                uint32_t bh0 = sB[0][nr][kp], bh1 = sB[0][nr][kp+4];
                uint32_t bl0 = sB[1][nr][kp], bl1 = sB[1][nr][kp+4];
                #pragma unroll
                for (int fm = 0; fm < 2; fm++){
                    mma_bf16(acc[fm][fn], a[fm][0], bh0, bh1);
                    mma_bf16(acc[fm][fn], a[fm][0], bl0, bl1);
                    mma_bf16(acc[fm][fn], a[fm][1], bh0, bh1);
                }
            }
        }
        __syncthreads();
    }
    #pragma unroll
    for (int fm = 0; fm < 2; fm++){
        int r = m0 + wm*32 + fm*16 + g;
        #pragma unroll
        for (int fn = 0; fn < 8; fn++){
            int cn = n0 + wn*64 + fn*8 + q*2;
            float b0 = bias[cn], b1 = bias[cn+1];
            float2 v0 = make_float2(acc[fm][fn][0] + b0, acc[fm][fn][1] + b1);
            float2 v1 = make_float2(acc[fm][fn][2] + b0, acc[fm][fn][3] + b1);
            *reinterpret_cast<float2*>(C + (size_t)r*NG + cn) = v0;
            *reinterpret_cast<float2*>(C + (size_t)(r+8)*NG + cn) = v1;
        }
    }
}

// fp32 GEMM (decoder constants)
__global__ void gemm_k(const float* __restrict__ A, const float* __restrict__ B,
                       const float* __restrict__ bias, float* __restrict__ C,
                       int M, int N, int K)
{
    __shared__ float As[8][128];
    __shared__ float Bs[8][128];
    int tid = threadIdx.x;
    int m0 = blockIdx.y*128, n0 = blockIdx.x*128;
    int tx = tid & 15, ty = tid >> 4;
    float acc[8][8];
    #pragma unroll
    for (int i = 0; i < 8; i++)
        #pragma unroll
        for (int j = 0; j < 8; j++) acc[i][j] = 0.f;
    int arow = tid >> 1, acol = (tid & 1)*4;
    int brow = tid >> 5, bcol = (tid & 31)*4;
    for (int k0 = 0; k0 < K; k0 += 8){
        float4 av = make_float4(0.f,0.f,0.f,0.f);
        int gm = m0 + arow;
        if (gm < M) av = *reinterpret_cast<const float4*>(A + (size_t)gm*K + k0 + acol);
        As[acol+0][arow] = av.x; As[acol+1][arow] = av.y;
        As[acol+2][arow] = av.z; As[acol+3][arow] = av.w;
        *reinterpret_cast<float4*>(&Bs[brow][bcol]) =
            *reinterpret_cast<const float4*>(B + (size_t)(k0+brow)*N + n0 + bcol);
        __syncthreads();
        #pragma unroll
        for (int kk = 0; kk < 8; kk++){
            float a[8], b[8];
            *reinterpret_cast<float4*>(a)   = *reinterpret_cast<float4*>(&As[kk][ty*4]);
            *reinterpret_cast<float4*>(a+4) = *reinterpret_cast<float4*>(&As[kk][64+ty*4]);
            *reinterpret_cast<float4*>(b)   = *reinterpret_cast<float4*>(&Bs[kk][tx*4]);
            *reinterpret_cast<float4*>(b+4) = *reinterpret_cast<float4*>(&Bs[kk][64+tx*4]);
            #pragma unroll
            for (int i = 0; i < 8; i++)
                #pragma unroll
                for (int j = 0; j < 8; j++) acc[i][j] += a[i]*b[j];
        }
        __syncthreads();
    }
    #pragma unroll
    for (int i = 0; i < 8; i++){
        int gm = m0 + ((i < 4) ? (ty*4 + i) : (64 + ty*4 + (i-4)));
        if (gm >= M) continue;
        #pragma unroll
        for (int j = 0; j < 8; j++){
            int gn = n0 + ((j < 4) ? (tx*4 + j) : (64 + tx*4 + (j-4)));
            C[(size_t)gm*N + gn] = acc[i][j] + bias[gn];
        }
    }
}

// ---------------------------------------------------------------------------
// Persistent tensor-core encoder layer: 64 steps, one launch, 88 blocks.
// ---------------------------------------------------------------------------
extern __shared__ uint32_t sdyn[];

__global__ void __launch_bounds__(256, 1) enc_tc_k(
    const float* __restrict__ X,
    const __nv_bfloat16* __restrict__ WHi, const __nv_bfloat16* __restrict__ WLo,
    float* __restrict__ Y, float* __restrict__ Cfin,
    __nv_bfloat16* __restrict__ Hhi, __nv_bfloat16* __restrict__ Hlo)
{
    uint32_t* sB = sdyn;
    uint32_t* sA = sdyn + SB_WORDS;
    float* sG = reinterpret_cast<float*>(sA);
    const int tid = threadIdx.x;
    const int lane = tid & 31, wid = tid >> 5;
    const int wm = wid & 1, wn = wid >> 1;
    const int g = lane >> 2, q = lane & 3;
    const int rt = blockIdx.x % 11, ct = blockIdx.x / 11;
    const int m0 = rt*ER, n0 = ct*EC;
    const unsigned nb = gridDim.x;
    unsigned round = 0;

    for (int i = tid; i < 2*128*32; i += 256){
        int s = i >> 12;
        int rem = i & 4095;
        int row = rem >> 5, w4 = rem & 31;
        const uint4* src = reinterpret_cast<const uint4*>(
            (s ? WLo : WHi) + (size_t)(n0 + row)*HH) + w4;
        *reinterpret_cast<uint4*>(&sB[s*128*BP + row*BP + w4*4]) = *src;
    }
    __syncthreads();

    const int erow = tid >> 2;
    const int hb = (tid & 3)*8;
    float c[8];
    #pragma unroll
    for (int e = 0; e < 8; e++) c[e] = 0.f;

    for (int t = 0; t < 64; t++){
        if (t > 0){
            for (int i = tid; i < 2*64*32; i += 256){
                int s = i >> 11;
                int rem = i & 2047;
                int row = rem >> 5, w4 = rem & 31;
                const uint4* src = reinterpret_cast<const uint4*>(
                    (s ? Hlo : Hhi) + ((size_t)(t-1)*GT + m0 + row)*HH) + w4;
                uint4 v = __ldcg(src);
                *reinterpret_cast<uint4*>(&sA[s*64*AP + row*AP + w4*4]) = v;
            }
            __syncthreads();
            float acc[2][4][4];
            #pragma unroll
            for (int i = 0; i < 2; i++)
                #pragma unroll
                for (int j = 0; j < 4; j++){ acc[i][j][0]=0.f; acc[i][j][1]=0.f; acc[i][j][2]=0.f; acc[i][j][3]=0.f; }
            #pragma unroll
            for (int ks = 0; ks < 16; ks++){
                const int kp = ks*8 + q;
                uint32_t a[2][2][4];
                #pragma unroll
                for (int fm = 0; fm < 2; fm++){
                    int row = wm*32 + fm*16;
                    #pragma unroll
                    for (int s = 0; s < 2; s++){
                        const uint32_t* base = sA + s*64*AP;
                        a[fm][s][0] = base[(row+g)*AP + kp];
                        a[fm][s][1] = base[(row+g+8)*AP + kp];
                        a[fm][s][2] = base[(row+g)*AP + kp+4];
                        a[fm][s][3] = base[(row+g+8)*AP + kp+4];
                    }
                }
                #pragma unroll
                for (int fn = 0; fn < 4; fn++){
                    int nr = wn*32 + fn*8 + g;
                    uint32_t bh0 = sB[nr*BP + kp], bh1 = sB[nr*BP + kp+4];
                    uint32_t bl0 = sB[128*BP + nr*BP + kp], bl1 = sB[128*BP + nr*BP + kp+4];
                    #pragma unroll
                    for (int fm = 0; fm < 2; fm++){
                        mma_bf16(acc[fm][fn], a[fm][0], bh0, bh1);
                        mma_bf16(acc[fm][fn], a[fm][0], bl0, bl1);
                        mma_bf16(acc[fm][fn], a[fm][1], bh0, bh1);
                    }
                }
            }
            __syncthreads();
            #pragma unroll
            for (int fm = 0; fm < 2; fm++){
                int r1 = wm*32 + fm*16 + g;
                #pragma unroll
                for (int fn = 0; fn < 4; fn++){
                    int c0 = wn*32 + fn*8 + q*2;
                    *reinterpret_cast<float2*>(&sG[r1*AP + c0]) =
                        make_float2(acc[fm][fn][0], acc[fm][fn][1]);
                    *reinterpret_cast<float2*>(&sG[(r1+8)*AP + c0]) =
                        make_float2(acc[fm][fn][2], acc[fm][fn][3]);
                }
            }
            __syncthreads();
        }
        const float* xp = X + ((size_t)t*GT + m0 + erow)*NG + n0;
        const size_t yb = ((size_t)t*GT + m0 + erow)*HH + ct*32 + hb;
        #pragma unroll
        for (int ep = 0; ep < 4; ep++){
            int h2 = (hb >> 1) + ep;
            int cb = h2*8;
            float4 x0 = *reinterpret_cast<const float4*>(xp + cb);
            float4 x1 = *reinterpret_cast<const float4*>(xp + cb + 4);
            float gi0 = x0.x, gi1 = x0.y, gf0 = x0.z, gf1 = x0.w;
            float gg0 = x1.x, gg1 = x1.y, go0 = x1.z, go1 = x1.w;
            if (t > 0){
                float4 s0 = *reinterpret_cast<const float4*>(&sG[erow*AP + cb]);
                float4 s1 = *reinterpret_cast<const float4*>(&sG[erow*AP + cb + 4]);
                gi0 += s0.x; gi1 += s0.y; gf0 += s0.z; gf1 += s0.w;
                gg0 += s1.x; gg1 += s1.y; go0 += s1.z; go1 += s1.w;
            }
            float c0 = sigmoidf(gf0)*c[ep*2]   + sigmoidf(gi0)*tanhf(gg0);
            float c1 = sigmoidf(gf1)*c[ep*2+1] + sigmoidf(gi1)*tanhf(gg1);
            c[ep*2] = c0; c[ep*2+1] = c1;
            float h0 = sigmoidf(go0)*tanhf(c0);
            float h1 = sigmoidf(go1)*tanhf(c1);
            *reinterpret_cast<float2*>(Y + yb + 2*ep) = make_float2(h0, h1);
            __nv_bfloat16 b0 = __float2bfloat16(h0), b1 = __float2bfloat16(h1);
            __nv_bfloat162 hhv; hhv.x = b0; hhv.y = b1;
            __nv_bfloat162 llv;
            llv.x = __float2bfloat16(h0 - __bfloat162float(b0));
            llv.y = __float2bfloat16(h1 - __bfloat162float(b1));
            *reinterpret_cast<__nv_bfloat162*>(Hhi + yb + 2*ep) = hhv;
            *reinterpret_cast<__nv_bfloat162*>(Hlo + yb + 2*ep) = llv;
        }
        grid_barrier(nb, round);
    }
    const size_t cbse = (size_t)(m0 + erow)*HH + ct*32 + hb;
    #pragma unroll
    for (int e = 0; e < 8; e++) Cfin[cbse + 2*(e>>1) + (e&1)] = c[e];
}

__global__ void snap_k(const float* __restrict__ Yt, const float* __restrict__ C,
                       const int* __restrict__ tord, float* dh, float* dc)
{
    int b = blockIdx.x, h = threadIdx.x;
    int row = (*tord)*64 + b;
    dh[b*HH + h] = Yt[(size_t)row*HH + h];
    dc[b*HH + h] = C[(size_t)row*HH + h];
}

__global__ void attn_k(const float* __restrict__ Y3, const float* __restrict__ attnW,
                       float* __restrict__ attn)
{
    int b = blockIdx.x, tid = threadIdx.x;
    __shared__ float wae[HH];
    __shared__ float sc[GT];
    __shared__ float red[256];
    wae[tid] = attnW[HH + tid];
    __syncthreads();
    for (int idx = tid; idx < GT; idx += 256){
        int g = idx % GG, t = idx / GG;
        const float* row = Y3 + ((size_t)(t*GT + g*64 + b))*HH;
        float s = 0.f;
        #pragma unroll 4
        for (int h = 0; h < HH; h++) s += row[h]*wae[h];
        sc[idx] = s;
    }
    __syncthreads();
    float mx = -1e30f;
    for (int idx = tid; idx < GT; idx += 256) mx = fmaxf(mx, sc[idx]);
    red[tid] = mx; __syncthreads();
    for (int s = 128; s > 0; s >>= 1){ if (tid < s) red[tid] = fmaxf(red[tid], red[tid+s]); __syncthreads(); }
    mx = red[0]; __syncthreads();
    float sm = 0.f;
    for (int idx = tid; idx < GT; idx += 256){ float e = expf(sc[idx]-mx); sc[idx] = e; sm += e; }
    red[tid] = sm; __syncthreads();
    for (int s = 128; s > 0; s >>= 1){ if (tid < s) red[tid] += red[tid+s]; __syncthreads(); }
    float inv = 1.f/red[0];
    __syncthreads();
    float a0 = 0.f;
    for (int idx = 0; idx < GT; idx++){
        int g = idx % GG, t = idx / GG;
        a0 += sc[idx]*Y3[((size_t)(t*GT + g*64 + b))*HH + tid];
    }
    attn[b*HH + tid] = a0*inv;
}

__global__ void pack_cin_k(const float* dh0, const float* attn, float* cin)
{
    int b = blockIdx.x, k = threadIdx.x;
    cin[b*512 + k] = (k < HH) ? dh0[b*HH + k] : attn[b*HH + (k - HH)];
}

// Persistent decoder: 64 steps x 4 layers, one launch. 96 blocks x 256 thr.
// Block = 16 rows x 32 h-cols.
__global__ __launch_bounds__(256, 2) void dec_persist_k(
    const float* __restrict__ x, const int* __restrict__ tord,
    const float* __restrict__ cnst, const float* __restrict__ cinAll,
    const float* __restrict__ WeT, const float* __restrict__ WihsT,
    float* __restrict__ H1, float* __restrict__ H2,
    const float* __restrict__ outW, const float* __restrict__ outB,
    const float* __restrict__ Wemb, const float* __restrict__ bemb,
    float* __restrict__ dout)
{
    __shared__ float sE[16][128];
    __shared__ float sIn[16][33];
    __shared__ float sW[32][4][32];
    __shared__ float sRed[16][16];
    __shared__ float sOut[16][4];
    const int tid = threadIdx.x;
    const int tx = tid & 31, ty = tid >> 5;      // 8 warps, 2 rows each
    const int jc = blockIdx.x & 7;
    const int m0 = (blockIdx.x >> 3)*16, j0 = jc*32;
    const unsigned nb = gridDim.x;
    unsigned round = 0;
    const int tordv = *tord;
    const int j = j0 + tx;
    for (int t = 0; t < 64; t++){
        if (t == 0){
            for (int idx = tid; idx < 16*128; idx += 256){
                int rr = idx >> 7, e = idx & 127;
                int m = m0 + rr;
                const float* xr = x + (((size_t)((m & 63)*TT_ + 63))*GG + (tordv + (m >> 6)))*FF;
                float v = bemb[e] + xr[0]*Wemb[e*4] + xr[1]*Wemb[e*4+1]
                                  + xr[2]*Wemb[e*4+2] + xr[3]*Wemb[e*4+3];
                sE[rr][e] = fmaxf(v, 0.f);
            }
            __syncthreads();
        } else {
            {
                int r = tid >> 4, sub = tid & 15, o = sub & 3, seg = sub >> 2;
                const float* hrow = H2 + (size_t)(m0 + r)*HH;
                float s = 0.f;
                #pragma unroll 4
                for (int h = seg*64; h < seg*64 + 64; h++)
                    s += __ldcg(hrow + h) * outW[o*HH + h];
                sRed[r][sub] = s;
            }
            __syncthreads();
            if (tid < 64){
                int rr = tid >> 2, oo = tid & 3;
                float v = sRed[rr][oo] + sRed[rr][4+oo] + sRed[rr][8+oo] + sRed[rr][12+oo] + outB[oo];
                sOut[rr][oo] = v;
                if (jc == 0){
                    int m = m0 + rr;
                    dout[(size_t)(m & 63)*(TT_*NT*FF) + (size_t)(t-1)*(NT*FF) + (m >> 6)*FF + oo] = v;
                }
            }
            __syncthreads();
            for (int idx = tid; idx < 16*128; idx += 256){
                int rr = idx >> 7, e = idx & 127;
                float v = bemb[e] + sOut[rr][0]*Wemb[e*4] + sOut[rr][1]*Wemb[e*4+1]
                        + sOut[rr][2]*Wemb[e*4+2] + sOut[rr][3]*Wemb[e*4+3];
                sE[rr][e] = fmaxf(v, 0.f);
            }
            __syncthreads();
        }
        for (int l = 0; l < 4; l++){
            float acc[2][4] = {{0.f,0.f,0.f,0.f},{0.f,0.f,0.f,0.f}};
            const float* Wt = (l == 0) ? WeT : (WihsT + (size_t)(l-1)*KSZ);
            const int K = (l == 0) ? EE : HH;
            const float* In = (l == 2) ? H2 : H1;
            float* Ho = (l == 0 || l == 2) ? H1 : H2;
            for (int k0 = 0; k0 < K; k0 += 32){
                if (l > 0 && tid < 128){
                    int r = tid >> 3, kc = (tid & 7)*4;
                    float4 v = __ldcg(reinterpret_cast<const float4*>(In + (size_t)(m0+r)*HH + k0 + kc));
                    sIn[r][kc] = v.x; sIn[r][kc+1] = v.y; sIn[r][kc+2] = v.z; sIn[r][kc+3] = v.w;
                }
                #pragma unroll
                for (int qq = 0; qq < 16; qq++){
                    int lin = qq*256 + tid;
                    int kr = lin >> 7, col = lin & 127;
                    sW[kr][col >> 5][col & 31] =
                        Wt[(size_t)(k0+kr)*NG + (col >> 5)*HH + j0 + (col & 31)];
                }
                __syncthreads();
                #pragma unroll
                for (int kk = 0; kk < 32; kk++){
                    float w0 = sW[kk][0][tx], w1 = sW[kk][1][tx];
                    float w2 = sW[kk][2][tx], w3 = sW[kk][3][tx];
                    float a0 = (l == 0) ? sE[ty*2][k0+kk]   : sIn[ty*2][kk];
                    float a1 = (l == 0) ? sE[ty*2+1][k0+kk] : sIn[ty*2+1][kk];
                    acc[0][0]+=a0*w0; acc[0][1]+=a0*w1; acc[0][2]+=a0*w2; acc[0][3]+=a0*w3;
                    acc[1][0]+=a1*w0; acc[1][1]+=a1*w1; acc[1][2]+=a1*w2; acc[1][3]+=a1*w3;
                }
                __syncthreads();
            }
            const float* cl = cnst + (size_t)l*BB*NG;
            const float* ci = cinAll + (size_t)l*BB*HH;
            #pragma unroll
            for (int rr = 0; rr < 2; rr++){
                int m = m0 + ty*2 + rr, b = m & 63;
                const float* cp = cl + (size_t)b*NG;
                float gi = acc[rr][0] + cp[j];
                float gf = acc[rr][1] + cp[HH + j];
                float gg = acc[rr][2] + cp[2*HH + j];
                float go = acc[rr][3] + cp[3*HH + j];
                float c2 = sigmoidf(gf)*ci[b*HH + j] + sigmoidf(gi)*tanhf(gg);
                Ho[(size_t)m*HH + j] = sigmoidf(go)*tanhf(c2);
            }
            grid_barrier(nb, round);
        }
    }
    {
        int r = tid >> 4, sub = tid & 15, o = sub & 3, seg = sub >> 2;
        const float* hrow = H2 + (size_t)(m0 + r)*HH;
        float s = 0.f;
        #pragma unroll 4
        for (int h = seg*64; h < seg*64 + 64; h++)
            s += __ldcg(hrow + h) * outW[o*HH + h];
        sRed[r][sub] = s;
    }
    __syncthreads();
    if (tid < 64 && jc == 0){
        int rr = tid >> 2, oo = tid & 3;
        float v = sRed[rr][oo] + sRed[rr][4+oo] + sRed[rr][8+oo] + sRed[rr][12+oo] + outB[oo];
        int m = m0 + rr;
        dout[(size_t)(m & 63)*(TT_*NT*FF) + 63u*(NT*FF) + (m >> 6)*FF + oo] = v;
    }
}

static float* symaddr(const void* sym)
{
    void* p = nullptr;
    cudaGetSymbolAddress(&p, sym);
    return (float*)p;
}

extern "C" void kernel_launch(void* const* d_in, const int* in_sizes, int n_in,
                              void* d_out, int out_size)
{
    (void)in_sizes; (void)n_in; (void)out_size;
    const float* x       = (const float*)d_in[0];
    const float* encLinW = (const float*)d_in[2];
    const float* encLinB = (const float*)d_in[3];
    const float* encWih0 = (const float*)d_in[4];
    const float* encWihs = (const float*)d_in[5];
    const float* encWhh  = (const float*)d_in[6];
    const float* encBih  = (const float*)d_in[7];
    const float* encBhh  = (const float*)d_in[8];
    const float* decEmbW = (const float*)d_in[9];
    const float* decEmbB = (const float*)d_in[10];
    const float* attnW   = (const float*)d_in[11];
    const float* decWih0 = (const float*)d_in[13];
    const float* decWihs = (const float*)d_in[14];
    const float* decWhh  = (const float*)d_in[15];
    const float* decBih  = (const float*)d_in[16];
    const float* decBhh  = (const float*)d_in[17];
    const float* outW    = (const float*)d_in[18];
    const float* outB    = (const float*)d_in[19];
    const int*   tord    = (const int*)d_in[20];
    float* out = (float*)d_out;

    float* pX = symaddr(g_X);
    float* pY = symaddr(g_Y0);
    float* pC = symaddr(g_Cst);
    __nv_bfloat16* pAhi = (__nv_bfloat16*)symaddr(g_Ahi);
    __nv_bfloat16* pAlo = (__nv_bfloat16*)symaddr(g_Alo);
    __nv_bfloat16* pWihHi = (__nv_bfloat16*)symaddr(g_WihHi);
    __nv_bfloat16* pWihLo = (__nv_bfloat16*)symaddr(g_WihLo);
    __nv_bfloat16* pWhhHi = (__nv_bfloat16*)symaddr(g_WhhHi);
    __nv_bfloat16* pWhhLo = (__nv_bfloat16*)symaddr(g_WhhLo);
    float* pBiasEncP = symaddr(g_biasEncP);
    float* pDecWihsT = symaddr(g_decWihsT);
    float* pDecWhhT = symaddr(g_decWhhT);
    float* pPack = symaddr(g_WcPack);
    float* pWeT = symaddr(g_decWeT);
    float* pBiasDec = symaddr(g_biasDec);
    float* pDech = symaddr(g_dech);
    float* pDecc = symaddr(g_decc);
    float* pAttn = symaddr(g_attn);
    float* pCin = symaddr(g_cin);
    float* pConst = symaddr(g_const);
    float* pH1 = symaddr(g_h1);
    float* pH2 = symaddr(g_h2);

    cudaFuncSetAttribute(enc_tc_k, cudaFuncAttributeMaxDynamicSharedMemorySize, SMEM_ENC);

    dim3 tb(32, 8);
    wsplit_perm_k<<<(NG*EE + 255)/256, 256>>>(encWih0, EE, pWihHi, pWihLo);
    for (int l = 1; l < 4; l++)
        wsplit_perm_k<<<(NG*HH + 255)/256, 256>>>(encWihs + (size_t)(l-1)*NG*HH, HH,
                                                  pWihHi + NG*EE + (size_t)(l-1)*NG*HH,
                                                  pWihLo + NG*EE + (size_t)(l-1)*NG*HH);
    for (int l = 0; l < 4; l++)
        wsplit_perm_k<<<(NG*HH + 255)/256, 256>>>(encWhh + (size_t)l*NG*HH, HH,
                                                  pWhhHi + (size_t)l*NG*HH,
                                                  pWhhLo + (size_t)l*NG*HH);
    for (int l = 0; l < 4; l++)
        addv_perm_k<<<4, 256>>>(encBih + l*NG, encBhh + l*NG, pBiasEncP + l*NG);
    for (int l = 0; l < 3; l++)
        transpose_k<<<dim3(8, 32), tb>>>(decWihs + (size_t)l*NG*HH, HH, NG, HH, pDecWihsT + (size_t)l*KSZ, NG);
    for (int l = 1; l < 4; l++)
        transpose_k<<<dim3(8, 32), tb>>>(decWhh + (size_t)l*NG*HH, HH, NG, HH, pDecWhhT + (size_t)(l-1)*KSZ, NG);
    transpose_k<<<dim3(8, 32), tb>>>(decWhh, HH, NG, HH, pPack, NG);
    transpose_k<<<dim3(8, 32), tb>>>(decWih0, 384, NG, HH, pPack + (size_t)HH*NG, NG);
    transpose_k<<<dim3(4, 32), tb>>>(decWih0 + HH, 384, NG, EE, pWeT, NG);
    addv_k<<<16, 256>>>(decBih, decBhh, pBiasDec, 4*NG);

    emb_k<<<MTOT, 128>>>(x, encLinW, encLinB, pAhi, pAlo);

    for (int l = 0; l < 4; l++){
        const __nv_bfloat16* wh = (l == 0) ? pWihHi : (pWihHi + NG*EE + (size_t)(l-1)*NG*HH);
        const __nv_bfloat16* wl = (l == 0) ? pWihLo : (pWihLo + NG*EE + (size_t)(l-1)*NG*HH);
        int Kin = (l == 0) ? EE : HH;
        gemm_tc_k<<<dim3(8, MTOT/128), 256>>>(pAhi, pAlo, wh, wl, pBiasEncP + l*NG, pX, Kin);
        reset_barrier_k<<<1, 1>>>();
        enc_tc_k<<<88, 256, SMEM_ENC>>>(pX, pWhhHi + (size_t)l*NG*HH, pWhhLo + (size_t)l*NG*HH,
                                        pY, pC, pAhi, pAlo);
        snap_k<<<64, 256>>>(pY + (size_t)(TT_-1)*GT*HH, pC, tord,
                            pDech + (size_t)l*BB*HH, pDecc + (size_t)l*BB*HH);
    }

    attn_k<<<BB, 256>>>(pY, attnW, pAttn);
    pack_cin_k<<<BB, 512>>>(pDech, pAttn, pCin);
    gemm_k<<<dim3(8, 1), 256>>>(pCin, pPack, pBiasDec, pConst, BB, NG, 512);
    for (int l = 1; l < 4; l++)
        gemm_k<<<dim3(8, 1), 256>>>(pDech + (size_t)l*BB*HH, pDecWhhT + (size_t)(l-1)*KSZ,
                                    pBiasDec + l*NG, pConst + (size_t)l*BB*NG, BB, NG, HH);

    reset_barrier_k<<<1, 1>>>();
    dec_persist_k<<<96, 256>>>(x, tord, pConst, pDecc, pWeT, pDecWihsT,
                               pH1, pH2, outW, outB, decEmbW, decEmbB, out);
}